// round 1
// baseline (speedup 1.0000x reference)
#include <cuda_runtime.h>

#define NN 50000
#define NE 800000
#define D 64
#define LL 4
#define GG 128
#define TT 10
#define NEG_SLOPE 0.2f
#define EPSV 1e-16f

// ---------------- scratch (static __device__, no allocs) ----------------
__device__ int   g_deg[NN];
__device__ int   g_rowptr[NN + 1];
__device__ int   g_cursor[NN];
__device__ int   g_csr[NE];        // packed (attr<<24) | src
__device__ float g_alpha[NE];      // alpha, then exp(alpha-m)
__device__ float g_hA[NN * D];
__device__ float g_hB[NN * D];
__device__ float g_gbuf[NN * D];
__device__ float g_asrc[NN];
__device__ float g_adst[NN];
__device__ float g_ewalpha[LL * 4];
__device__ float g_pooled[GG * D];

// ---------------- zero scratch ----------------
__global__ void zero_kernel() {
    int i = blockIdx.x * blockDim.x + threadIdx.x;
    if (i < NN) g_deg[i] = 0;
    if (i < GG * D) g_pooled[i] = 0.f;
}

// ---------------- precompute per-(layer,attr) edge attention scalar ----------------
// ew_alpha[l][a] = edge_embs[l][a] . (W_edges[l]^T @ att_edge[l])
__global__ void pre_kernel(const float* __restrict__ edge_embs,
                           const float* __restrict__ W_edges,
                           const float* __restrict__ att_edge) {
    __shared__ float sv[LL][D];
    int tid = threadIdx.x;           // 256 threads
    int l = tid >> 6, j = tid & 63;
    float v = 0.f;
    #pragma unroll
    for (int k = 0; k < D; k++)
        v += att_edge[l * D + k] * W_edges[l * D * D + k * D + j];
    sv[l][j] = v;
    __syncthreads();
    if (tid < 16) {
        int ll = tid >> 2, a = tid & 3;
        float s = 0.f;
        for (int jj = 0; jj < D; jj++)
            s += edge_embs[ll * 4 * D + a * D + jj] * sv[ll][jj];
        g_ewalpha[ll * 4 + a] = s;
    }
}

// ---------------- CSR build ----------------
__global__ void hist_kernel(const int* __restrict__ dst) {
    int e = blockIdx.x * blockDim.x + threadIdx.x;
    if (e < NE) atomicAdd(&g_deg[dst[e]], 1);
}

__global__ void scan_kernel() {  // single block, 1024 threads
    __shared__ int buf[1024];
    __shared__ int carry;
    int tid = threadIdx.x;
    if (tid == 0) { carry = 0; g_rowptr[0] = 0; }
    __syncthreads();
    for (int base = 0; base < NN; base += 1024) {
        int idx = base + tid;
        int v = (idx < NN) ? g_deg[idx] : 0;
        buf[tid] = v;
        __syncthreads();
        for (int off = 1; off < 1024; off <<= 1) {
            int t = (tid >= off) ? buf[tid - off] : 0;
            __syncthreads();
            buf[tid] += t;
            __syncthreads();
        }
        int incl = buf[tid] + carry;
        if (idx < NN) { g_rowptr[idx + 1] = incl; g_cursor[idx] = incl - v; }
        __syncthreads();
        if (tid == 1023) carry = incl;
        __syncthreads();
    }
}

__global__ void scatter_kernel(const int* __restrict__ src,
                               const int* __restrict__ dst,
                               const int* __restrict__ attr) {
    int e = blockIdx.x * blockDim.x + threadIdx.x;
    if (e < NE) {
        int pos = atomicAdd(&g_cursor[dst[e]], 1);
        g_csr[pos] = (attr[e] << 24) | src[e];
    }
}

// ---------------- per-layer node GEMM: g = h @ W^T, asrc = g.a_src, adst = g.a_dst ----------------
// 256 threads = 4 nodes x 64 features
__global__ void gemm_kernel(int layer,
                            const int* __restrict__ x,
                            const float* __restrict__ emb,
                            const float* __restrict__ Ws,
                            const float* __restrict__ att_src,
                            const float* __restrict__ att_dst,
                            const float* __restrict__ biases) {
    __shared__ float sW[D][D + 1];   // transposed: sW[k][j] = W[j][k]
    __shared__ float sh[4][D];
    __shared__ float red_s[8], red_d[8];

    const float* W = Ws + layer * D * D;
    const float* a_s = att_src + layer * D;
    const float* a_d = att_dst + layer * D;
    const float* in_h = (layer == 0) ? nullptr
                        : (((layer - 1) & 1) == 0 ? g_hA : g_hB);
    const float* bias = (layer == 0) ? nullptr : biases + (layer - 1) * D;

    int tid = threadIdx.x;
    for (int idx = tid; idx < D * D; idx += 256) {
        int j = idx >> 6, k = idx & 63;
        sW[k][j] = W[idx];
    }
    int slot = tid >> 6;
    int j = tid & 63;
    int node = blockIdx.x * 4 + slot;
    float hv = 0.f;
    if (node < NN) {
        if (in_h) hv = fmaxf(in_h[node * D + j] + bias[j], 0.f);
        else      hv = emb[x[node] * D + j];
    }
    sh[slot][j] = hv;
    __syncthreads();

    float acc = 0.f;
    #pragma unroll
    for (int k = 0; k < D; k++)
        acc = fmaf(sh[slot][k], sW[k][j], acc);

    float ps = acc * a_s[j];
    float pd = acc * a_d[j];
    #pragma unroll
    for (int off = 16; off; off >>= 1) {
        ps += __shfl_down_sync(0xFFFFFFFFu, ps, off);
        pd += __shfl_down_sync(0xFFFFFFFFu, pd, off);
    }
    int wid = tid >> 5;
    if ((tid & 31) == 0) { red_s[wid] = ps; red_d[wid] = pd; }
    if (node < NN) g_gbuf[node * D + j] = acc;
    __syncthreads();
    if (tid < 4) {
        int n2 = blockIdx.x * 4 + tid;
        if (n2 < NN) {
            g_asrc[n2] = red_s[2 * tid] + red_s[2 * tid + 1];
            g_adst[n2] = red_d[2 * tid] + red_d[2 * tid + 1];
        }
    }
}

// ---------------- aggregation: one warp per dst node ----------------
__global__ void agg_kernel(int layer) {
    int gwarp = (blockIdx.x * blockDim.x + threadIdx.x) >> 5;
    int lane = threadIdx.x & 31;
    if (gwarp >= NN) return;
    int n = gwarp;

    const float* ewa = g_ewalpha + layer * 4;
    float* out_h = ((layer & 1) == 0) ? g_hA : g_hB;

    int start = g_rowptr[n];
    int end   = g_rowptr[n + 1];
    float adst_n = g_adst[n];

    // pass 1: alpha + max
    float m = -1e30f;
    for (int e = start + lane; e < end; e += 32) {
        int p = g_csr[e];
        int src = p & 0x00FFFFFF;
        int attr = p >> 24;
        float a = g_asrc[src] + adst_n + ewa[attr];
        a = (a > 0.f) ? a : NEG_SLOPE * a;
        g_alpha[e] = a;
        m = fmaxf(m, a);
    }
    #pragma unroll
    for (int off = 16; off; off >>= 1)
        m = fmaxf(m, __shfl_xor_sync(0xFFFFFFFFu, m, off));

    // pass 2: exp + sum (overwrite alpha with ex)
    float s = 0.f;
    for (int e = start + lane; e < end; e += 32) {
        float ex = __expf(g_alpha[e] - m);
        g_alpha[e] = ex;
        s += ex;
    }
    #pragma unroll
    for (int off = 16; off; off >>= 1)
        s += __shfl_xor_sync(0xFFFFFFFFu, s, off);
    float inv = 1.f / (s + EPSV);

    // pass 3: weighted gather of g[src]
    float acc0 = 0.f, acc1 = 0.f;
    for (int base = start; base < end; base += 32) {
        int cnt = min(32, end - base);
        float w = 0.f;
        int src = 0;
        if (lane < cnt) {
            int p = g_csr[base + lane];
            src = p & 0x00FFFFFF;
            w = g_alpha[base + lane] * inv;
        }
        for (int jj = 0; jj < cnt; jj++) {
            float wj = __shfl_sync(0xFFFFFFFFu, w, jj);
            int sj   = __shfl_sync(0xFFFFFFFFu, src, jj);
            const float* gr = g_gbuf + sj * D;
            acc0 = fmaf(wj, gr[lane],      acc0);
            acc1 = fmaf(wj, gr[lane + 32], acc1);
        }
    }
    out_h[n * D + lane]      = acc0;
    out_h[n * D + lane + 32] = acc1;
}

// ---------------- pooling (fused last bias+relu) ----------------
__global__ void pool_kernel(const int* __restrict__ batch,
                            const float* __restrict__ biases) {
    int idx = blockIdx.x * blockDim.x + threadIdx.x;
    if (idx >= NN * D) return;
    int n = idx >> 6, j = idx & 63;
    float v = fmaxf(g_hB[idx] + biases[3 * D + j], 0.f);
    atomicAdd(&g_pooled[batch[n] * D + j], v);
}

// ---------------- final MLP ----------------
__global__ void mlp_kernel(const float* __restrict__ W1, const float* __restrict__ b1,
                           const float* __restrict__ W2, const float* __restrict__ b2,
                           float* __restrict__ out) {
    __shared__ float sp[D];
    __shared__ float shid[2 * D];
    int g = blockIdx.x;
    int tid = threadIdx.x;  // 128 threads
    if (tid < D) sp[tid] = g_pooled[g * D + tid];
    __syncthreads();
    float hsum = b1[tid];
    #pragma unroll
    for (int k = 0; k < D; k++)
        hsum = fmaf(sp[k], W1[tid * D + k], hsum);
    shid[tid] = fmaxf(hsum, 0.f);
    __syncthreads();
    if (tid < TT) {
        float o = b2[tid];
        #pragma unroll
        for (int k = 0; k < 2 * D; k++)
            o = fmaf(shid[k], W2[tid * 2 * D + k], o);
        out[g * TT + tid] = o;
    }
}

// ---------------- launch ----------------
extern "C" void kernel_launch(void* const* d_in, const int* in_sizes, int n_in,
                              void* d_out, int out_size) {
    const int*   x         = (const int*)  d_in[0];
    const int*   edge_idx  = (const int*)  d_in[1];
    const int*   edge_attr = (const int*)  d_in[2];
    const int*   batch     = (const int*)  d_in[3];
    const float* node_emb  = (const float*)d_in[4];
    const float* edge_embs = (const float*)d_in[5];
    const float* Ws        = (const float*)d_in[6];
    const float* W_edges   = (const float*)d_in[7];
    const float* att_src   = (const float*)d_in[8];
    const float* att_dst   = (const float*)d_in[9];
    const float* att_edge  = (const float*)d_in[10];
    const float* biases    = (const float*)d_in[11];
    const float* W1        = (const float*)d_in[12];
    const float* b1        = (const float*)d_in[13];
    const float* W2        = (const float*)d_in[14];
    const float* b2        = (const float*)d_in[15];
    float* out = (float*)d_out;

    const int* src = edge_idx;
    const int* dst = edge_idx + NE;

    zero_kernel<<<(NN + 255) / 256, 256>>>();
    pre_kernel<<<1, 256>>>(edge_embs, W_edges, att_edge);
    hist_kernel<<<(NE + 255) / 256, 256>>>(dst);
    scan_kernel<<<1, 1024>>>();
    scatter_kernel<<<(NE + 255) / 256, 256>>>(src, dst, edge_attr);

    for (int l = 0; l < LL; l++) {
        gemm_kernel<<<(NN + 3) / 4, 256>>>(l, x, node_emb, Ws, att_src, att_dst, biases);
        agg_kernel<<<(NN * 32 + 255) / 256, 256>>>(l);
    }

    pool_kernel<<<(NN * D + 255) / 256, 256>>>(batch, biases);
    mlp_kernel<<<GG, 2 * D>>>(W1, b1, W2, b2, out);
}

// round 2
// speedup vs baseline: 1.5297x; 1.5297x over previous
#include <cuda_runtime.h>

#define NN 50000
#define NE 800000
#define D 64
#define LL 4
#define GG 128
#define TT 10
#define NEG_SLOPE 0.2f
#define EPSV 1e-16f
#define NBLK ((NN + 255) / 256)   // 196

// ---------------- scratch (static __device__, no allocs) ----------------
__device__ int   g_deg[NN];
__device__ int   g_rowptr[NN + 1];
__device__ int   g_cursor[NN];
__device__ int   g_partial[NBLK];
__device__ int   g_csr[NE];        // packed (attr<<24) | src
__device__ float g_alpha[NE];      // fallback path scratch
__device__ float g_hA[NN * D];
__device__ float g_hB[NN * D];
__device__ float g_gbuf[NN * D];
__device__ float g_asrc[NN];
__device__ float g_adst[NN];
__device__ float g_ewalpha[LL * 4];
__device__ float g_pooled[GG * D];

// ---------------- zero scratch ----------------
__global__ void zero_kernel() {
    int i = blockIdx.x * blockDim.x + threadIdx.x;
    if (i < NN) g_deg[i] = 0;
    if (i < GG * D) g_pooled[i] = 0.f;
}

// ---------------- precompute per-(layer,attr) edge attention scalar ----------------
__global__ void pre_kernel(const float* __restrict__ edge_embs,
                           const float* __restrict__ W_edges,
                           const float* __restrict__ att_edge) {
    __shared__ float sv[LL][D];
    int tid = threadIdx.x;           // 256 threads
    int l = tid >> 6, j = tid & 63;
    float v = 0.f;
    #pragma unroll
    for (int k = 0; k < D; k++)
        v += att_edge[l * D + k] * W_edges[l * D * D + k * D + j];
    sv[l][j] = v;
    __syncthreads();
    if (tid < 16) {
        int ll = tid >> 2, a = tid & 3;
        float s = 0.f;
        for (int jj = 0; jj < D; jj++)
            s += edge_embs[ll * 4 * D + a * D + jj] * sv[ll][jj];
        g_ewalpha[ll * 4 + a] = s;
    }
}

// ---------------- CSR build ----------------
__global__ void hist_kernel(const int* __restrict__ dst) {
    int e = blockIdx.x * blockDim.x + threadIdx.x;
    if (e < NE) atomicAdd(&g_deg[dst[e]], 1);
}

__device__ __forceinline__ int warp_incl_scan(int x, int lane) {
    #pragma unroll
    for (int off = 1; off < 32; off <<= 1) {
        int t = __shfl_up_sync(0xFFFFFFFFu, x, off);
        if (lane >= off) x += t;
    }
    return x;
}

// per-block inclusive scan of deg; block totals to g_partial
__global__ void scan1_kernel() {
    __shared__ int wsum[8];
    int tid = threadIdx.x, lane = tid & 31, warp = tid >> 5;
    int idx = blockIdx.x * 256 + tid;
    int v = (idx < NN) ? g_deg[idx] : 0;
    int x = warp_incl_scan(v, lane);
    if (lane == 31) wsum[warp] = x;
    __syncthreads();
    if (tid < 8) {
        int s = wsum[tid];
        #pragma unroll
        for (int off = 1; off < 8; off <<= 1) {
            int t = __shfl_up_sync(0xFFu, s, off);
            if (tid >= off) s += t;
        }
        wsum[tid] = s;
    }
    __syncthreads();
    int incl = x + (warp ? wsum[warp - 1] : 0);
    if (idx < NN) g_rowptr[idx + 1] = incl;      // block-local inclusive
    if (tid == 255) g_partial[blockIdx.x] = incl;
}

// exclusive scan of 196 block totals (single block, 256 threads)
__global__ void scan2_kernel() {
    __shared__ int wsum[8];
    int tid = threadIdx.x, lane = tid & 31, warp = tid >> 5;
    int v = (tid < NBLK) ? g_partial[tid] : 0;
    int x = warp_incl_scan(v, lane);
    if (lane == 31) wsum[warp] = x;
    __syncthreads();
    if (tid < 8) {
        int s = wsum[tid];
        #pragma unroll
        for (int off = 1; off < 8; off <<= 1) {
            int t = __shfl_up_sync(0xFFu, s, off);
            if (tid >= off) s += t;
        }
        wsum[tid] = s;
    }
    __syncthreads();
    int incl = x + (warp ? wsum[warp - 1] : 0);
    if (tid < NBLK) g_partial[tid] = incl - v;    // exclusive
}

// add offsets, produce rowptr + cursor
__global__ void scan3_kernel() {
    int idx = blockIdx.x * blockDim.x + threadIdx.x;
    if (idx < NN) {
        int r = g_rowptr[idx + 1] + g_partial[idx >> 8];
        g_rowptr[idx + 1] = r;
        g_cursor[idx] = r - g_deg[idx];
    }
    if (idx == 0) g_rowptr[0] = 0;
}

__global__ void scatter_kernel(const int* __restrict__ src,
                               const int* __restrict__ dst,
                               const int* __restrict__ attr) {
    int e = blockIdx.x * blockDim.x + threadIdx.x;
    if (e < NE) {
        int pos = atomicAdd(&g_cursor[dst[e]], 1);
        g_csr[pos] = (attr[e] << 24) | src[e];
    }
}

// ---------------- per-layer node GEMM: 4x4 register-tiled ----------------
// block = 256 threads handles 64 nodes x 64 features
__global__ void __launch_bounds__(256) gemm_kernel(
        int layer,
        const int* __restrict__ x,
        const float* __restrict__ emb,
        const float* __restrict__ Ws,
        const float* __restrict__ att_src,
        const float* __restrict__ att_dst,
        const float* __restrict__ biases) {
    __shared__ float shT[64][68];     // shT[k][n_local]  (k-major, padded for f4 align)
    __shared__ float sWT[64][68];     // sWT[k][j] = W[j][k]
    __shared__ float sred[2][16][64]; // asrc / adst partials

    const float* W = Ws + layer * D * D;
    const float* in_h = (layer == 0) ? nullptr
                        : (((layer - 1) & 1) == 0 ? g_hA : g_hB);
    const float* bias = (layer == 0) ? nullptr : biases + (layer - 1) * D;
    const float* a_s = att_src + layer * D;
    const float* a_d = att_dst + layer * D;

    int tid = threadIdx.x;
    int nb = blockIdx.x * 64;

    for (int idx = tid; idx < D * D; idx += 256) {
        sWT[idx & 63][idx >> 6] = W[idx];
    }
    for (int idx = tid; idx < 64 * D; idx += 256) {
        int nl = idx >> 6, k = idx & 63;
        int node = nb + nl;
        float hv = 0.f;
        if (node < NN) {
            hv = in_h ? fmaxf(in_h[node * D + k] + bias[k], 0.f)
                      : emb[x[node] * D + k];
        }
        shT[k][nl] = hv;
    }
    __syncthreads();

    int tx = tid & 15;   // node group: local nodes tx*4 .. tx*4+3
    int ty = tid >> 4;   // feature group: j = ty*4 .. ty*4+3
    int n0 = tx * 4;
    int j0 = ty * 4;

    float acc[4][4] = {};
    #pragma unroll 8
    for (int k = 0; k < 64; k++) {
        float4 hv = *(const float4*)&shT[k][n0];
        float4 wv = *(const float4*)&sWT[k][j0];
        acc[0][0] = fmaf(hv.x, wv.x, acc[0][0]);
        acc[0][1] = fmaf(hv.x, wv.y, acc[0][1]);
        acc[0][2] = fmaf(hv.x, wv.z, acc[0][2]);
        acc[0][3] = fmaf(hv.x, wv.w, acc[0][3]);
        acc[1][0] = fmaf(hv.y, wv.x, acc[1][0]);
        acc[1][1] = fmaf(hv.y, wv.y, acc[1][1]);
        acc[1][2] = fmaf(hv.y, wv.z, acc[1][2]);
        acc[1][3] = fmaf(hv.y, wv.w, acc[1][3]);
        acc[2][0] = fmaf(hv.z, wv.x, acc[2][0]);
        acc[2][1] = fmaf(hv.z, wv.y, acc[2][1]);
        acc[2][2] = fmaf(hv.z, wv.z, acc[2][2]);
        acc[2][3] = fmaf(hv.z, wv.w, acc[2][3]);
        acc[3][0] = fmaf(hv.w, wv.x, acc[3][0]);
        acc[3][1] = fmaf(hv.w, wv.y, acc[3][1]);
        acc[3][2] = fmaf(hv.w, wv.z, acc[3][2]);
        acc[3][3] = fmaf(hv.w, wv.w, acc[3][3]);
    }

    // attention dot-product partials
    float as0 = a_s[j0], as1 = a_s[j0 + 1], as2 = a_s[j0 + 2], as3 = a_s[j0 + 3];
    float ad0 = a_d[j0], ad1 = a_d[j0 + 1], ad2 = a_d[j0 + 2], ad3 = a_d[j0 + 3];
    #pragma unroll
    for (int i = 0; i < 4; i++) {
        float sa = acc[i][0] * as0 + acc[i][1] * as1 + acc[i][2] * as2 + acc[i][3] * as3;
        float sd = acc[i][0] * ad0 + acc[i][1] * ad1 + acc[i][2] * ad2 + acc[i][3] * ad3;
        sred[0][ty][n0 + i] = sa;
        sred[1][ty][n0 + i] = sd;
        int node = nb + n0 + i;
        if (node < NN) {
            *(float4*)&g_gbuf[node * D + j0] =
                make_float4(acc[i][0], acc[i][1], acc[i][2], acc[i][3]);
        }
    }
    __syncthreads();
    if (tid < 64) {
        float s = 0.f, dsum = 0.f;
        #pragma unroll
        for (int t = 0; t < 16; t++) {
            s    += sred[0][t][tid];
            dsum += sred[1][t][tid];
        }
        int node = nb + tid;
        if (node < NN) { g_asrc[node] = s; g_adst[node] = dsum; }
    }
}

// ---------------- aggregation: one warp per dst node, fused single pass ----------------
__global__ void agg_kernel(int layer) {
    int gwarp = (blockIdx.x * blockDim.x + threadIdx.x) >> 5;
    int lane = threadIdx.x & 31;
    if (gwarp >= NN) return;
    int n = gwarp;

    const float* ewa = g_ewalpha + layer * 4;
    float* out_h = ((layer & 1) == 0) ? g_hA : g_hB;

    int start = g_rowptr[n];
    int end   = g_rowptr[n + 1];
    int deg   = end - start;
    float2* outp = (float2*)(out_h + n * D);

    if (deg == 0) {
        outp[lane] = make_float2(0.f, 0.f);
        return;
    }

    float adst_n = g_adst[n];
    float2 acc = make_float2(0.f, 0.f);

    if (deg <= 128) {
        // -------- fast path: everything register-resident --------
        int   srcs[4];
        float av[4];
        float m = -1e30f;
        #pragma unroll
        for (int i = 0; i < 4; i++) {
            int e = start + lane + 32 * i;
            if (e < end) {
                int p = __ldg(&g_csr[e]);
                srcs[i] = p & 0x00FFFFFF;
                float a = g_asrc[srcs[i]] + adst_n + ewa[p >> 24];
                a = (a > 0.f) ? a : NEG_SLOPE * a;
                av[i] = a;
                m = fmaxf(m, a);
            } else { srcs[i] = 0; av[i] = -1e30f; }
        }
        #pragma unroll
        for (int off = 16; off; off >>= 1)
            m = fmaxf(m, __shfl_xor_sync(0xFFFFFFFFu, m, off));

        float s = 0.f;
        #pragma unroll
        for (int i = 0; i < 4; i++) {
            av[i] = __expf(av[i] - m);   // invalid slots underflow to 0
            s += av[i];
        }
        #pragma unroll
        for (int off = 16; off; off >>= 1)
            s += __shfl_xor_sync(0xFFFFFFFFu, s, off);
        float inv = 1.f / (s + EPSV);

        #pragma unroll
        for (int i = 0; i < 4; i++) {
            int rem = deg - 32 * i;
            if (rem <= 0) break;
            int cnt = rem < 32 ? rem : 32;
            float w = av[i] * inv;
            for (int jj = 0; jj < cnt; jj++) {
                float wj = __shfl_sync(0xFFFFFFFFu, w, jj);
                int   sj = __shfl_sync(0xFFFFFFFFu, srcs[i], jj);
                float2 v = ((const float2*)(g_gbuf + sj * D))[lane];
                acc.x = fmaf(wj, v.x, acc.x);
                acc.y = fmaf(wj, v.y, acc.y);
            }
        }
    } else {
        // -------- fallback: 3 passes via g_alpha --------
        float m = -1e30f;
        for (int e = start + lane; e < end; e += 32) {
            int p = g_csr[e];
            float a = g_asrc[p & 0x00FFFFFF] + adst_n + ewa[p >> 24];
            a = (a > 0.f) ? a : NEG_SLOPE * a;
            g_alpha[e] = a;
            m = fmaxf(m, a);
        }
        #pragma unroll
        for (int off = 16; off; off >>= 1)
            m = fmaxf(m, __shfl_xor_sync(0xFFFFFFFFu, m, off));
        float s = 0.f;
        for (int e = start + lane; e < end; e += 32) {
            float ex = __expf(g_alpha[e] - m);
            g_alpha[e] = ex;
            s += ex;
        }
        #pragma unroll
        for (int off = 16; off; off >>= 1)
            s += __shfl_xor_sync(0xFFFFFFFFu, s, off);
        float inv = 1.f / (s + EPSV);

        for (int base = start; base < end; base += 32) {
            int cnt = min(32, end - base);
            float w = 0.f; int src = 0;
            if (lane < cnt) {
                int p = g_csr[base + lane];
                src = p & 0x00FFFFFF;
                w = g_alpha[base + lane] * inv;
            }
            for (int jj = 0; jj < cnt; jj++) {
                float wj = __shfl_sync(0xFFFFFFFFu, w, jj);
                int   sj = __shfl_sync(0xFFFFFFFFu, src, jj);
                float2 v = ((const float2*)(g_gbuf + sj * D))[lane];
                acc.x = fmaf(wj, v.x, acc.x);
                acc.y = fmaf(wj, v.y, acc.y);
            }
        }
    }
    outp[lane] = acc;
}

// ---------------- pooling (fused last bias+relu) ----------------
__global__ void pool_kernel(const int* __restrict__ batch,
                            const float* __restrict__ biases) {
    int idx = blockIdx.x * blockDim.x + threadIdx.x;
    if (idx >= NN * D) return;
    int n = idx >> 6, j = idx & 63;
    float v = fmaxf(g_hB[idx] + biases[3 * D + j], 0.f);
    atomicAdd(&g_pooled[batch[n] * D + j], v);
}

// ---------------- final MLP ----------------
__global__ void mlp_kernel(const float* __restrict__ W1, const float* __restrict__ b1,
                           const float* __restrict__ W2, const float* __restrict__ b2,
                           float* __restrict__ out) {
    __shared__ float sp[D];
    __shared__ float shid[2 * D];
    int g = blockIdx.x;
    int tid = threadIdx.x;  // 128 threads
    if (tid < D) sp[tid] = g_pooled[g * D + tid];
    __syncthreads();
    float hsum = b1[tid];
    #pragma unroll
    for (int k = 0; k < D; k++)
        hsum = fmaf(sp[k], W1[tid * D + k], hsum);
    shid[tid] = fmaxf(hsum, 0.f);
    __syncthreads();
    if (tid < TT) {
        float o = b2[tid];
        #pragma unroll
        for (int k = 0; k < 2 * D; k++)
            o = fmaf(shid[k], W2[tid * 2 * D + k], o);
        out[g * TT + tid] = o;
    }
}

// ---------------- launch ----------------
extern "C" void kernel_launch(void* const* d_in, const int* in_sizes, int n_in,
                              void* d_out, int out_size) {
    const int*   x         = (const int*)  d_in[0];
    const int*   edge_idx  = (const int*)  d_in[1];
    const int*   edge_attr = (const int*)  d_in[2];
    const int*   batch     = (const int*)  d_in[3];
    const float* node_emb  = (const float*)d_in[4];
    const float* edge_embs = (const float*)d_in[5];
    const float* Ws        = (const float*)d_in[6];
    const float* W_edges   = (const float*)d_in[7];
    const float* att_src   = (const float*)d_in[8];
    const float* att_dst   = (const float*)d_in[9];
    const float* att_edge  = (const float*)d_in[10];
    const float* biases    = (const float*)d_in[11];
    const float* W1        = (const float*)d_in[12];
    const float* b1        = (const float*)d_in[13];
    const float* W2        = (const float*)d_in[14];
    const float* b2        = (const float*)d_in[15];
    float* out = (float*)d_out;

    const int* src = edge_idx;
    const int* dst = edge_idx + NE;

    zero_kernel<<<(NN + 255) / 256, 256>>>();
    pre_kernel<<<1, 256>>>(edge_embs, W_edges, att_edge);
    hist_kernel<<<(NE + 255) / 256, 256>>>(dst);
    scan1_kernel<<<NBLK, 256>>>();
    scan2_kernel<<<1, 256>>>();
    scan3_kernel<<<(NN + 255) / 256, 256>>>();
    scatter_kernel<<<(NE + 255) / 256, 256>>>(src, dst, edge_attr);

    for (int l = 0; l < LL; l++) {
        gemm_kernel<<<(NN + 63) / 64, 256>>>(l, x, node_emb, Ws, att_src, att_dst, biases);
        agg_kernel<<<(NN * 32 + 255) / 256, 256>>>(l);
    }

    pool_kernel<<<(NN * D + 255) / 256, 256>>>(batch, biases);
    mlp_kernel<<<GG, 2 * D>>>(W1, b1, W2, b2, out);
}

// round 3
// speedup vs baseline: 1.6502x; 1.0788x over previous
#include <cuda_runtime.h>

#define NN 50000
#define NE 800000
#define D 64
#define LL 4
#define GG 128
#define TT 10
#define NEG_SLOPE 0.2f
#define EPSV 1e-16f
#define NBLK ((NN + 255) / 256)   // 196

// ---------------- scratch (static __device__, no allocs) ----------------
__device__ int   g_deg[NN];
__device__ int   g_rowptr[NN + 1];
__device__ int   g_cursor[NN];
__device__ int   g_partial[NBLK];
__device__ int   g_csr[NE];        // packed (attr<<24) | src
__device__ float g_alpha[NE];      // fallback path scratch
__device__ float g_hA[NN * D];
__device__ float g_hB[NN * D];
__device__ float g_gbuf[NN * D];
__device__ float g_asrc[NN];
__device__ float g_adst[NN];
__device__ float g_ewalpha[LL * 4];
__device__ float g_pooled[GG * D];

// ---------------- zero scratch + fused ewalpha precompute ----------------
__global__ void zero_pre_kernel(const float* __restrict__ edge_embs,
                                const float* __restrict__ W_edges,
                                const float* __restrict__ att_edge) {
    int i = blockIdx.x * blockDim.x + threadIdx.x;
    if (i < NN) g_deg[i] = 0;
    if (i < GG * D) g_pooled[i] = 0.f;

    if (blockIdx.x == 0) {
        __shared__ float sv[LL][D];
        int tid = threadIdx.x;           // 256 threads
        int l = tid >> 6, j = tid & 63;
        float v = 0.f;
        #pragma unroll
        for (int k = 0; k < D; k++)
            v += att_edge[l * D + k] * W_edges[l * D * D + k * D + j];
        sv[l][j] = v;
        __syncthreads();
        if (tid < 16) {
            int ll = tid >> 2, a = tid & 3;
            float s = 0.f;
            for (int jj = 0; jj < D; jj++)
                s += edge_embs[ll * 4 * D + a * D + jj] * sv[ll][jj];
            g_ewalpha[ll * 4 + a] = s;
        }
    }
}

// ---------------- CSR build ----------------
__global__ void hist_kernel(const int* __restrict__ dst) {
    int e = blockIdx.x * blockDim.x + threadIdx.x;
    if (e < NE) atomicAdd(&g_deg[dst[e]], 1);
}

__device__ __forceinline__ int warp_incl_scan(int x, int lane) {
    #pragma unroll
    for (int off = 1; off < 32; off <<= 1) {
        int t = __shfl_up_sync(0xFFFFFFFFu, x, off);
        if (lane >= off) x += t;
    }
    return x;
}

__global__ void scan1_kernel() {
    __shared__ int wsum[8];
    int tid = threadIdx.x, lane = tid & 31, warp = tid >> 5;
    int idx = blockIdx.x * 256 + tid;
    int v = (idx < NN) ? g_deg[idx] : 0;
    int x = warp_incl_scan(v, lane);
    if (lane == 31) wsum[warp] = x;
    __syncthreads();
    if (tid < 8) {
        int s = wsum[tid];
        #pragma unroll
        for (int off = 1; off < 8; off <<= 1) {
            int t = __shfl_up_sync(0xFFu, s, off);
            if (tid >= off) s += t;
        }
        wsum[tid] = s;
    }
    __syncthreads();
    int incl = x + (warp ? wsum[warp - 1] : 0);
    if (idx < NN) g_rowptr[idx + 1] = incl;      // block-local inclusive
    if (tid == 255) g_partial[blockIdx.x] = incl;
}

__global__ void scan2_kernel() {
    __shared__ int wsum[8];
    int tid = threadIdx.x, lane = tid & 31, warp = tid >> 5;
    int v = (tid < NBLK) ? g_partial[tid] : 0;
    int x = warp_incl_scan(v, lane);
    if (lane == 31) wsum[warp] = x;
    __syncthreads();
    if (tid < 8) {
        int s = wsum[tid];
        #pragma unroll
        for (int off = 1; off < 8; off <<= 1) {
            int t = __shfl_up_sync(0xFFu, s, off);
            if (tid >= off) s += t;
        }
        wsum[tid] = s;
    }
    __syncthreads();
    int incl = x + (warp ? wsum[warp - 1] : 0);
    if (tid < NBLK) g_partial[tid] = incl - v;    // exclusive
}

__global__ void scan3_kernel() {
    int idx = blockIdx.x * blockDim.x + threadIdx.x;
    if (idx < NN) {
        int r = g_rowptr[idx + 1] + g_partial[idx >> 8];
        g_rowptr[idx + 1] = r;
        g_cursor[idx] = r - g_deg[idx];
    }
    if (idx == 0) g_rowptr[0] = 0;
}

__global__ void scatter_kernel(const int* __restrict__ src,
                               const int* __restrict__ dst,
                               const int* __restrict__ attr) {
    int e = blockIdx.x * blockDim.x + threadIdx.x;
    if (e < NE) {
        int pos = atomicAdd(&g_cursor[dst[e]], 1);
        g_csr[pos] = (attr[e] << 24) | src[e];
    }
}

// ---------------- per-layer node GEMM: 4x4 register-tiled ----------------
__global__ void __launch_bounds__(256) gemm_kernel(
        int layer,
        const int* __restrict__ x,
        const float* __restrict__ emb,
        const float* __restrict__ Ws,
        const float* __restrict__ att_src,
        const float* __restrict__ att_dst,
        const float* __restrict__ biases) {
    __shared__ float shT[64][68];     // shT[k][n_local]
    __shared__ float sWT[64][68];     // sWT[k][j] = W[j][k]
    __shared__ float sred[2][16][64];

    const float* W = Ws + layer * D * D;
    const float* in_h = (layer == 0) ? nullptr
                        : (((layer - 1) & 1) == 0 ? g_hA : g_hB);
    const float* bias = (layer == 0) ? nullptr : biases + (layer - 1) * D;
    const float* a_s = att_src + layer * D;
    const float* a_d = att_dst + layer * D;

    int tid = threadIdx.x;
    int nb = blockIdx.x * 64;

    for (int idx = tid; idx < D * D; idx += 256) {
        sWT[idx & 63][idx >> 6] = W[idx];
    }
    for (int idx = tid; idx < 64 * D; idx += 256) {
        int nl = idx >> 6, k = idx & 63;
        int node = nb + nl;
        float hv = 0.f;
        if (node < NN) {
            hv = in_h ? fmaxf(in_h[node * D + k] + bias[k], 0.f)
                      : emb[x[node] * D + k];
        }
        shT[k][nl] = hv;
    }
    __syncthreads();

    int tx = tid & 15;
    int ty = tid >> 4;
    int n0 = tx * 4;
    int j0 = ty * 4;

    float acc[4][4] = {};
    #pragma unroll 8
    for (int k = 0; k < 64; k++) {
        float4 hv = *(const float4*)&shT[k][n0];
        float4 wv = *(const float4*)&sWT[k][j0];
        acc[0][0] = fmaf(hv.x, wv.x, acc[0][0]);
        acc[0][1] = fmaf(hv.x, wv.y, acc[0][1]);
        acc[0][2] = fmaf(hv.x, wv.z, acc[0][2]);
        acc[0][3] = fmaf(hv.x, wv.w, acc[0][3]);
        acc[1][0] = fmaf(hv.y, wv.x, acc[1][0]);
        acc[1][1] = fmaf(hv.y, wv.y, acc[1][1]);
        acc[1][2] = fmaf(hv.y, wv.z, acc[1][2]);
        acc[1][3] = fmaf(hv.y, wv.w, acc[1][3]);
        acc[2][0] = fmaf(hv.z, wv.x, acc[2][0]);
        acc[2][1] = fmaf(hv.z, wv.y, acc[2][1]);
        acc[2][2] = fmaf(hv.z, wv.z, acc[2][2]);
        acc[2][3] = fmaf(hv.z, wv.w, acc[2][3]);
        acc[3][0] = fmaf(hv.w, wv.x, acc[3][0]);
        acc[3][1] = fmaf(hv.w, wv.y, acc[3][1]);
        acc[3][2] = fmaf(hv.w, wv.z, acc[3][2]);
        acc[3][3] = fmaf(hv.w, wv.w, acc[3][3]);
    }

    float as0 = a_s[j0], as1 = a_s[j0 + 1], as2 = a_s[j0 + 2], as3 = a_s[j0 + 3];
    float ad0 = a_d[j0], ad1 = a_d[j0 + 1], ad2 = a_d[j0 + 2], ad3 = a_d[j0 + 3];
    #pragma unroll
    for (int i = 0; i < 4; i++) {
        float sa = acc[i][0] * as0 + acc[i][1] * as1 + acc[i][2] * as2 + acc[i][3] * as3;
        float sd = acc[i][0] * ad0 + acc[i][1] * ad1 + acc[i][2] * ad2 + acc[i][3] * ad3;
        sred[0][ty][n0 + i] = sa;
        sred[1][ty][n0 + i] = sd;
        int node = nb + n0 + i;
        if (node < NN) {
            *(float4*)&g_gbuf[node * D + j0] =
                make_float4(acc[i][0], acc[i][1], acc[i][2], acc[i][3]);
        }
    }
    __syncthreads();
    if (tid < 64) {
        float s = 0.f, dsum = 0.f;
        #pragma unroll
        for (int t = 0; t < 16; t++) {
            s    += sred[0][t][tid];
            dsum += sred[1][t][tid];
        }
        int node = nb + tid;
        if (node < NN) { g_asrc[node] = s; g_adst[node] = dsum; }
    }
}

// ---------------- aggregation: warp/node, 2 edges in flight, float4 gather ----------------
__global__ void agg_kernel(int layer) {
    const unsigned F = 0xFFFFFFFFu;
    int gwarp = (blockIdx.x * blockDim.x + threadIdx.x) >> 5;
    int lane = threadIdx.x & 31;
    if (gwarp >= NN) return;
    int n = gwarp;

    const float* ewa = g_ewalpha + layer * 4;
    float* out_h = ((layer & 1) == 0) ? g_hA : g_hB;

    int start = g_rowptr[n];
    int end   = g_rowptr[n + 1];
    int deg   = end - start;

    int half  = lane >> 4;        // 0: even edges, 1: odd edges
    int qlane = lane & 15;        // float4 column group
    float4 acc4 = make_float4(0.f, 0.f, 0.f, 0.f);

    if (deg == 0) {
        if (half == 0)
            *(float4*)(out_h + n * D + (qlane << 2)) = acc4;
        return;
    }

    float adst_n = g_adst[n];

    if (deg <= 128) {
        // -------- fast path: register-resident --------
        int   srcs[4];
        float av[4];
        float m = -1e30f;
        #pragma unroll
        for (int i = 0; i < 4; i++) {
            int e = start + lane + 32 * i;
            if (e < end) {
                int p = __ldg(&g_csr[e]);
                srcs[i] = p & 0x00FFFFFF;
                float a = g_asrc[srcs[i]] + adst_n + ewa[p >> 24];
                a = (a > 0.f) ? a : NEG_SLOPE * a;
                av[i] = a;
                m = fmaxf(m, a);
            } else { srcs[i] = 0; av[i] = -1e30f; }
        }
        #pragma unroll
        for (int off = 16; off; off >>= 1)
            m = fmaxf(m, __shfl_xor_sync(F, m, off));

        float s = 0.f;
        #pragma unroll
        for (int i = 0; i < 4; i++) {
            av[i] = __expf(av[i] - m);   // invalid slots -> 0
            s += av[i];
        }
        #pragma unroll
        for (int off = 16; off; off >>= 1)
            s += __shfl_xor_sync(F, s, off);
        float inv = 1.f / (s + EPSV);

        #pragma unroll
        for (int i = 0; i < 4; i++) {
            if (32 * i >= deg) break;
            int cnt = min(32, deg - 32 * i);
            float w = av[i] * inv;
            int   sv = srcs[i];
            #pragma unroll 2
            for (int t = 0; t < cnt; t += 2) {
                int e = t + half;                  // e <= 31; lane e may be pad (w=0, src=0)
                float wj = __shfl_sync(F, w, e);
                int   sj = __shfl_sync(F, sv, e);
                float4 v = *(const float4*)(g_gbuf + sj * D + (qlane << 2));
                acc4.x = fmaf(wj, v.x, acc4.x);
                acc4.y = fmaf(wj, v.y, acc4.y);
                acc4.z = fmaf(wj, v.z, acc4.z);
                acc4.w = fmaf(wj, v.w, acc4.w);
            }
        }
    } else {
        // -------- fallback: 3 passes via g_alpha --------
        float m = -1e30f;
        for (int e = start + lane; e < end; e += 32) {
            int p = g_csr[e];
            float a = g_asrc[p & 0x00FFFFFF] + adst_n + ewa[p >> 24];
            a = (a > 0.f) ? a : NEG_SLOPE * a;
            g_alpha[e] = a;
            m = fmaxf(m, a);
        }
        #pragma unroll
        for (int off = 16; off; off >>= 1)
            m = fmaxf(m, __shfl_xor_sync(F, m, off));
        float s = 0.f;
        for (int e = start + lane; e < end; e += 32) {
            float ex = __expf(g_alpha[e] - m);
            g_alpha[e] = ex;
            s += ex;
        }
        #pragma unroll
        for (int off = 16; off; off >>= 1)
            s += __shfl_xor_sync(F, s, off);
        float inv = 1.f / (s + EPSV);

        for (int base = start; base < end; base += 32) {
            int cnt = min(32, end - base);
            float w = 0.f; int sv = 0;
            if (lane < cnt) {
                int p = g_csr[base + lane];
                sv = p & 0x00FFFFFF;
                w = g_alpha[base + lane] * inv;
            }
            #pragma unroll 2
            for (int t = 0; t < cnt; t += 2) {
                int e = t + half;
                float wj = __shfl_sync(F, w, e);
                int   sj = __shfl_sync(F, sv, e);
                float4 v = *(const float4*)(g_gbuf + sj * D + (qlane << 2));
                acc4.x = fmaf(wj, v.x, acc4.x);
                acc4.y = fmaf(wj, v.y, acc4.y);
                acc4.z = fmaf(wj, v.z, acc4.z);
                acc4.w = fmaf(wj, v.w, acc4.w);
            }
        }
    }

    // combine halves: lanes 0-15 + lanes 16-31
    acc4.x += __shfl_xor_sync(F, acc4.x, 16);
    acc4.y += __shfl_xor_sync(F, acc4.y, 16);
    acc4.z += __shfl_xor_sync(F, acc4.z, 16);
    acc4.w += __shfl_xor_sync(F, acc4.w, 16);
    if (half == 0)
        *(float4*)(out_h + n * D + (qlane << 2)) = acc4;
}

// ---------------- pooling: sorted-batch run accumulation ----------------
// block handles 256 nodes; thread = (row 0..3, feature j); iterate rows +=4
__global__ void pool_kernel(const int* __restrict__ batch,
                            const float* __restrict__ biases) {
    int tid = threadIdx.x;
    int j = tid & 63;
    int r0 = tid >> 6;
    int nb = blockIdx.x * 256;
    float bj = biases[3 * D + j];

    float acc = 0.f;
    int cur = -1;
    for (int i = r0; i < 256; i += 4) {
        int n = nb + i;
        if (n >= NN) break;
        int b = __ldg(&batch[n]);
        float v = fmaxf(g_hB[n * D + j] + bj, 0.f);
        if (b != cur) {
            if (cur >= 0) atomicAdd(&g_pooled[cur * D + j], acc);
            acc = 0.f; cur = b;
        }
        acc += v;
    }
    if (cur >= 0) atomicAdd(&g_pooled[cur * D + j], acc);
}

// ---------------- final MLP ----------------
__global__ void mlp_kernel(const float* __restrict__ W1, const float* __restrict__ b1,
                           const float* __restrict__ W2, const float* __restrict__ b2,
                           float* __restrict__ out) {
    __shared__ float sp[D];
    __shared__ float shid[2 * D];
    int g = blockIdx.x;
    int tid = threadIdx.x;  // 128 threads
    if (tid < D) sp[tid] = g_pooled[g * D + tid];
    __syncthreads();
    float hsum = b1[tid];
    #pragma unroll
    for (int k = 0; k < D; k++)
        hsum = fmaf(sp[k], W1[tid * D + k], hsum);
    shid[tid] = fmaxf(hsum, 0.f);
    __syncthreads();
    if (tid < TT) {
        float o = b2[tid];
        #pragma unroll
        for (int k = 0; k < 2 * D; k++)
            o = fmaf(shid[k], W2[tid * 2 * D + k], o);
        out[g * TT + tid] = o;
    }
}

// ---------------- launch ----------------
extern "C" void kernel_launch(void* const* d_in, const int* in_sizes, int n_in,
                              void* d_out, int out_size) {
    const int*   x         = (const int*)  d_in[0];
    const int*   edge_idx  = (const int*)  d_in[1];
    const int*   edge_attr = (const int*)  d_in[2];
    const int*   batch     = (const int*)  d_in[3];
    const float* node_emb  = (const float*)d_in[4];
    const float* edge_embs = (const float*)d_in[5];
    const float* Ws        = (const float*)d_in[6];
    const float* W_edges   = (const float*)d_in[7];
    const float* att_src   = (const float*)d_in[8];
    const float* att_dst   = (const float*)d_in[9];
    const float* att_edge  = (const float*)d_in[10];
    const float* biases    = (const float*)d_in[11];
    const float* W1        = (const float*)d_in[12];
    const float* b1        = (const float*)d_in[13];
    const float* W2        = (const float*)d_in[14];
    const float* b2        = (const float*)d_in[15];
    float* out = (float*)d_out;

    const int* src = edge_idx;
    const int* dst = edge_idx + NE;

    zero_pre_kernel<<<(NN + 255) / 256, 256>>>(edge_embs, W_edges, att_edge);
    hist_kernel<<<(NE + 255) / 256, 256>>>(dst);
    scan1_kernel<<<NBLK, 256>>>();
    scan2_kernel<<<1, 256>>>();
    scan3_kernel<<<(NN + 255) / 256, 256>>>();
    scatter_kernel<<<(NE + 255) / 256, 256>>>(src, dst, edge_attr);

    for (int l = 0; l < LL; l++) {
        gemm_kernel<<<(NN + 63) / 64, 256>>>(l, x, node_emb, Ws, att_src, att_dst, biases);
        agg_kernel<<<(NN * 32 + 255) / 256, 256>>>(l);
    }

    pool_kernel<<<(NN + 255) / 256, 256>>>(batch, biases);
    mlp_kernel<<<GG, 2 * D>>>(W1, b1, W2, b2, out);
}

// round 5
// speedup vs baseline: 1.6643x; 1.0085x over previous
#include <cuda_runtime.h>

#define NN 50000
#define NE 800000
#define D 64
#define LL 4
#define GG 128
#define TT 10
#define NEG_SLOPE 0.2f
#define EPSV 1e-16f
#define NBLK ((NN + 255) / 256)   // 196
#define NV 21                     // node vocab size

// ---------------- scratch (static __device__, zero-init at load) ----------------
__device__ int   g_deg[NN];        // zeroed by scatter_kernel at end of each run
__device__ int   g_rowptr[NN + 1];
__device__ int   g_cursor[NN];
__device__ unsigned g_epoch;                    // monotonic run counter
__device__ volatile unsigned g_aggflag[NBLK];   // epoch-tagged publish flags
__device__ volatile int      g_aggval[NBLK];
__device__ int   g_csr[NE];        // packed (attr<<24) | src
__device__ float g_alpha[NE];      // fallback path scratch
__device__ float g_hA[NN * D];
__device__ float g_hB[NN * D];
__device__ float g_gbuf[NN * D];
__device__ float g_asrc[NN];
__device__ float g_adst[NN];
__device__ float g_ewalpha[LL * 4];
__device__ float g_pooled[GG * D]; // zeroed by mlp_kernel after reading
__device__ float g_gt[NV * D];     // layer-0 g table
__device__ float g_ast[NV];        // layer-0 asrc table
__device__ float g_adt[NV];        // layer-0 adst table

// ---------------- hist + epoch + ewalpha + layer-0 table ----------------
__global__ void hist_pre_kernel(const int* __restrict__ dst,
                                const float* __restrict__ edge_embs,
                                const float* __restrict__ W_edges,
                                const float* __restrict__ att_edge,
                                const float* __restrict__ node_emb,
                                const float* __restrict__ Ws,
                                const float* __restrict__ att_src,
                                const float* __restrict__ att_dst) {
    int tid = threadIdx.x;
    int e = blockIdx.x * 256 + tid;
    if (e < NE) atomicAdd(&g_deg[dst[e]], 1);
    if (blockIdx.x == 0 && tid == 0) atomicAdd(&g_epoch, 1u);

    if (blockIdx.x == gridDim.x - 1) {
        __shared__ float sv[LL][D];
        __shared__ float sgt[NV][D];
        int l = tid >> 6, j = tid & 63;
        float v = 0.f;
        #pragma unroll
        for (int k = 0; k < D; k++)
            v += att_edge[l * D + k] * W_edges[l * D * D + k * D + j];
        sv[l][j] = v;
        int vg = tid >> 6;
        for (int vv = vg; vv < NV; vv += 4) {
            float acc = 0.f;
            #pragma unroll
            for (int k = 0; k < D; k++)
                acc = fmaf(node_emb[vv * D + k], Ws[j * D + k], acc);
            sgt[vv][j] = acc;
            g_gt[vv * D + j] = acc;
        }
        __syncthreads();
        if (tid < 16) {
            int ll = tid >> 2, a = tid & 3;
            float s = 0.f;
            for (int jj = 0; jj < D; jj++)
                s += edge_embs[ll * 4 * D + a * D + jj] * sv[ll][jj];
            g_ewalpha[ll * 4 + a] = s;
        }
        if (tid < NV) {
            float s = 0.f, dd = 0.f;
            #pragma unroll
            for (int jj = 0; jj < D; jj++) {
                s  += sgt[tid][jj] * att_src[jj];
                dd += sgt[tid][jj] * att_dst[jj];
            }
            g_ast[tid] = s;
            g_adt[tid] = dd;
        }
    }
}

// ---------------- single-kernel scan (publish + spin) + layer-0 fill ----------------
__global__ void scanfill_kernel(const int* __restrict__ x) {
    __shared__ int wsum[8];
    __shared__ int soffset;
    __shared__ __align__(16) float sgt[NV * D];   // 16B aligned: accessed as float4
    int tid = threadIdx.x, lane = tid & 31, warp = tid >> 5;
    int b = blockIdx.x;
    unsigned epoch = g_epoch;

    int idx = b * 256 + tid;
    int v = (idx < NN) ? g_deg[idx] : 0;
    int xx = v;
    #pragma unroll
    for (int off = 1; off < 32; off <<= 1) {
        int t = __shfl_up_sync(0xFFFFFFFFu, xx, off);
        if (lane >= off) xx += t;
    }
    if (lane == 31) wsum[warp] = xx;
    __syncthreads();
    if (tid < 8) {
        int s = wsum[tid];
        #pragma unroll
        for (int off = 1; off < 8; off <<= 1) {
            int t = __shfl_up_sync(0xFFu, s, off);
            if (tid >= off) s += t;
        }
        wsum[tid] = s;
    }
    __syncthreads();
    int incl = xx + (warp ? wsum[warp - 1] : 0);

    if (tid == 255) {
        g_aggval[b] = incl;
        __threadfence();
        g_aggflag[b] = epoch;
    }
    if (warp == 0) {
        int sum = 0;
        for (int jj = lane; jj < b; jj += 32) {
            while (g_aggflag[jj] < epoch) { }
            sum += g_aggval[jj];
        }
        #pragma unroll
        for (int off = 16; off; off >>= 1)
            sum += __shfl_xor_sync(0xFFFFFFFFu, sum, off);
        if (lane == 0) soffset = sum;
    }
    __syncthreads();
    int r = incl + soffset;
    if (idx < NN) {
        g_rowptr[idx + 1] = r;
        g_cursor[idx] = r - v;
    }
    if (b == 0 && tid == 0) g_rowptr[0] = 0;

    // ---- layer-0 fill: gbuf/asrc/adst from tables ----
    for (int i = tid; i < NV * D; i += 256) sgt[i] = g_gt[i];
    __syncthreads();
    if (idx < NN) {
        int xv = x[idx];
        g_asrc[idx] = g_ast[xv];
        g_adst[idx] = g_adt[xv];
    }
    int nb = b * 256;
    for (int i = tid; i < 256 * 16; i += 256) {
        int nl = i >> 4, q = i & 15;
        int node = nb + nl;
        if (node < NN) {
            int xv = __ldg(&x[node]);
            ((float4*)g_gbuf)[node * 16 + q] = ((const float4*)sgt)[xv * 16 + q];
        }
    }
}

// ---------------- scatter (+ zero g_deg for next run) ----------------
__global__ void scatter_kernel(const int* __restrict__ src,
                               const int* __restrict__ dst,
                               const int* __restrict__ attr) {
    int e = blockIdx.x * blockDim.x + threadIdx.x;
    if (e < NE) {
        int pos = atomicAdd(&g_cursor[dst[e]], 1);
        g_csr[pos] = (attr[e] << 24) | src[e];
    }
    if (e < NN) g_deg[e] = 0;
}

// ---------------- per-layer node GEMM (layers 1..3): 4x4 register-tiled ----------------
__global__ void __launch_bounds__(256) gemm_kernel(
        int layer,
        const float* __restrict__ Ws,
        const float* __restrict__ att_src,
        const float* __restrict__ att_dst,
        const float* __restrict__ biases) {
    __shared__ __align__(16) float shT[64][68];
    __shared__ __align__(16) float sWT[64][68];
    __shared__ float sred[2][16][64];

    const float* W = Ws + layer * D * D;
    const float* in_h = (((layer - 1) & 1) == 0) ? g_hA : g_hB;
    const float* bias = biases + (layer - 1) * D;
    const float* a_s = att_src + layer * D;
    const float* a_d = att_dst + layer * D;

    int tid = threadIdx.x;
    int nb = blockIdx.x * 64;

    for (int idx = tid; idx < D * D; idx += 256) {
        sWT[idx & 63][idx >> 6] = W[idx];
    }
    for (int idx = tid; idx < 64 * D; idx += 256) {
        int nl = idx >> 6, k = idx & 63;
        int node = nb + nl;
        float hv = 0.f;
        if (node < NN)
            hv = fmaxf(in_h[node * D + k] + bias[k], 0.f);
        shT[k][nl] = hv;
    }
    __syncthreads();

    int tx = tid & 15;
    int ty = tid >> 4;
    int n0 = tx * 4;
    int j0 = ty * 4;

    float acc[4][4] = {};
    #pragma unroll 8
    for (int k = 0; k < 64; k++) {
        float4 hv = *(const float4*)&shT[k][n0];
        float4 wv = *(const float4*)&sWT[k][j0];
        acc[0][0] = fmaf(hv.x, wv.x, acc[0][0]);
        acc[0][1] = fmaf(hv.x, wv.y, acc[0][1]);
        acc[0][2] = fmaf(hv.x, wv.z, acc[0][2]);
        acc[0][3] = fmaf(hv.x, wv.w, acc[0][3]);
        acc[1][0] = fmaf(hv.y, wv.x, acc[1][0]);
        acc[1][1] = fmaf(hv.y, wv.y, acc[1][1]);
        acc[1][2] = fmaf(hv.y, wv.z, acc[1][2]);
        acc[1][3] = fmaf(hv.y, wv.w, acc[1][3]);
        acc[2][0] = fmaf(hv.z, wv.x, acc[2][0]);
        acc[2][1] = fmaf(hv.z, wv.y, acc[2][1]);
        acc[2][2] = fmaf(hv.z, wv.z, acc[2][2]);
        acc[2][3] = fmaf(hv.z, wv.w, acc[2][3]);
        acc[3][0] = fmaf(hv.w, wv.x, acc[3][0]);
        acc[3][1] = fmaf(hv.w, wv.y, acc[3][1]);
        acc[3][2] = fmaf(hv.w, wv.z, acc[3][2]);
        acc[3][3] = fmaf(hv.w, wv.w, acc[3][3]);
    }

    float as0 = a_s[j0], as1 = a_s[j0 + 1], as2 = a_s[j0 + 2], as3 = a_s[j0 + 3];
    float ad0 = a_d[j0], ad1 = a_d[j0 + 1], ad2 = a_d[j0 + 2], ad3 = a_d[j0 + 3];
    #pragma unroll
    for (int i = 0; i < 4; i++) {
        float sa = acc[i][0] * as0 + acc[i][1] * as1 + acc[i][2] * as2 + acc[i][3] * as3;
        float sd = acc[i][0] * ad0 + acc[i][1] * ad1 + acc[i][2] * ad2 + acc[i][3] * ad3;
        sred[0][ty][n0 + i] = sa;
        sred[1][ty][n0 + i] = sd;
        int node = nb + n0 + i;
        if (node < NN) {
            *(float4*)&g_gbuf[node * D + j0] =
                make_float4(acc[i][0], acc[i][1], acc[i][2], acc[i][3]);
        }
    }
    __syncthreads();
    if (tid < 64) {
        float s = 0.f, dsum = 0.f;
        #pragma unroll
        for (int t = 0; t < 16; t++) {
            s    += sred[0][t][tid];
            dsum += sred[1][t][tid];
        }
        int node = nb + tid;
        if (node < NN) { g_asrc[node] = s; g_adst[node] = dsum; }
    }
}

// ---------------- aggregation: warp/node, 2 edges in flight, float4 gather ----------------
__global__ void agg_kernel(int layer) {
    const unsigned F = 0xFFFFFFFFu;
    int gwarp = (blockIdx.x * blockDim.x + threadIdx.x) >> 5;
    int lane = threadIdx.x & 31;
    if (gwarp >= NN) return;
    int n = gwarp;

    const float* ewa = g_ewalpha + layer * 4;
    float* out_h = ((layer & 1) == 0) ? g_hA : g_hB;

    int start = g_rowptr[n];
    int end   = g_rowptr[n + 1];
    int deg   = end - start;

    int half  = lane >> 4;
    int qlane = lane & 15;
    float4 acc4 = make_float4(0.f, 0.f, 0.f, 0.f);

    if (deg == 0) {
        if (half == 0)
            *(float4*)(out_h + n * D + (qlane << 2)) = acc4;
        return;
    }

    float adst_n = g_adst[n];

    if (deg <= 128) {
        int   srcs[4];
        float av[4];
        float m = -1e30f;
        #pragma unroll
        for (int i = 0; i < 4; i++) {
            int e = start + lane + 32 * i;
            if (e < end) {
                int p = __ldg(&g_csr[e]);
                srcs[i] = p & 0x00FFFFFF;
                float a = g_asrc[srcs[i]] + adst_n + ewa[p >> 24];
                a = (a > 0.f) ? a : NEG_SLOPE * a;
                av[i] = a;
                m = fmaxf(m, a);
            } else { srcs[i] = 0; av[i] = -1e30f; }
        }
        #pragma unroll
        for (int off = 16; off; off >>= 1)
            m = fmaxf(m, __shfl_xor_sync(F, m, off));

        float s = 0.f;
        #pragma unroll
        for (int i = 0; i < 4; i++) {
            av[i] = __expf(av[i] - m);
            s += av[i];
        }
        #pragma unroll
        for (int off = 16; off; off >>= 1)
            s += __shfl_xor_sync(F, s, off);
        float inv = 1.f / (s + EPSV);

        #pragma unroll
        for (int i = 0; i < 4; i++) {
            if (32 * i >= deg) break;
            int cnt = min(32, deg - 32 * i);
            float w = av[i] * inv;
            int   sv = srcs[i];
            #pragma unroll 2
            for (int t = 0; t < cnt; t += 2) {
                int e = t + half;
                float wj = __shfl_sync(F, w, e);
                int   sj = __shfl_sync(F, sv, e);
                float4 v = *(const float4*)(g_gbuf + sj * D + (qlane << 2));
                acc4.x = fmaf(wj, v.x, acc4.x);
                acc4.y = fmaf(wj, v.y, acc4.y);
                acc4.z = fmaf(wj, v.z, acc4.z);
                acc4.w = fmaf(wj, v.w, acc4.w);
            }
        }
    } else {
        float m = -1e30f;
        for (int e = start + lane; e < end; e += 32) {
            int p = g_csr[e];
            float a = g_asrc[p & 0x00FFFFFF] + adst_n + ewa[p >> 24];
            a = (a > 0.f) ? a : NEG_SLOPE * a;
            g_alpha[e] = a;
            m = fmaxf(m, a);
        }
        #pragma unroll
        for (int off = 16; off; off >>= 1)
            m = fmaxf(m, __shfl_xor_sync(F, m, off));
        float s = 0.f;
        for (int e = start + lane; e < end; e += 32) {
            float ex = __expf(g_alpha[e] - m);
            g_alpha[e] = ex;
            s += ex;
        }
        #pragma unroll
        for (int off = 16; off; off >>= 1)
            s += __shfl_xor_sync(F, s, off);
        float inv = 1.f / (s + EPSV);

        for (int base = start; base < end; base += 32) {
            int cnt = min(32, end - base);
            float w = 0.f; int sv = 0;
            if (lane < cnt) {
                int p = g_csr[base + lane];
                sv = p & 0x00FFFFFF;
                w = g_alpha[base + lane] * inv;
            }
            #pragma unroll 2
            for (int t = 0; t < cnt; t += 2) {
                int e = t + half;
                float wj = __shfl_sync(F, w, e);
                int   sj = __shfl_sync(F, sv, e);
                float4 v = *(const float4*)(g_gbuf + sj * D + (qlane << 2));
                acc4.x = fmaf(wj, v.x, acc4.x);
                acc4.y = fmaf(wj, v.y, acc4.y);
                acc4.z = fmaf(wj, v.z, acc4.z);
                acc4.w = fmaf(wj, v.w, acc4.w);
            }
        }
    }

    acc4.x += __shfl_xor_sync(F, acc4.x, 16);
    acc4.y += __shfl_xor_sync(F, acc4.y, 16);
    acc4.z += __shfl_xor_sync(F, acc4.z, 16);
    acc4.w += __shfl_xor_sync(F, acc4.w, 16);
    if (half == 0)
        *(float4*)(out_h + n * D + (qlane << 2)) = acc4;
}

// ---------------- pooling: sorted-batch run accumulation ----------------
__global__ void pool_kernel(const int* __restrict__ batch,
                            const float* __restrict__ biases) {
    int tid = threadIdx.x;
    int j = tid & 63;
    int r0 = tid >> 6;
    int nb = blockIdx.x * 256;
    float bj = biases[3 * D + j];

    float acc = 0.f;
    int cur = -1;
    for (int i = r0; i < 256; i += 4) {
        int n = nb + i;
        if (n >= NN) break;
        int b = __ldg(&batch[n]);
        float v = fmaxf(g_hB[n * D + j] + bj, 0.f);
        if (b != cur) {
            if (cur >= 0) atomicAdd(&g_pooled[cur * D + j], acc);
            acc = 0.f; cur = b;
        }
        acc += v;
    }
    if (cur >= 0) atomicAdd(&g_pooled[cur * D + j], acc);
}

// ---------------- final MLP (+ zero g_pooled for next run) ----------------
__global__ void mlp_kernel(const float* __restrict__ W1, const float* __restrict__ b1,
                           const float* __restrict__ W2, const float* __restrict__ b2,
                           float* __restrict__ out) {
    __shared__ float sp[D];
    __shared__ float shid[2 * D];
    int g = blockIdx.x;
    int tid = threadIdx.x;  // 128 threads
    if (tid < D) sp[tid] = g_pooled[g * D + tid];
    __syncthreads();
    if (tid < D) g_pooled[g * D + tid] = 0.f;   // reset for next run
    float hsum = b1[tid];
    #pragma unroll
    for (int k = 0; k < D; k++)
        hsum = fmaf(sp[k], W1[tid * D + k], hsum);
    shid[tid] = fmaxf(hsum, 0.f);
    __syncthreads();
    if (tid < TT) {
        float o = b2[tid];
        #pragma unroll
        for (int k = 0; k < 2 * D; k++)
            o = fmaf(shid[k], W2[tid * 2 * D + k], o);
        out[g * TT + tid] = o;
    }
}

// ---------------- launch ----------------
extern "C" void kernel_launch(void* const* d_in, const int* in_sizes, int n_in,
                              void* d_out, int out_size) {
    const int*   x         = (const int*)  d_in[0];
    const int*   edge_idx  = (const int*)  d_in[1];
    const int*   edge_attr = (const int*)  d_in[2];
    const int*   batch     = (const int*)  d_in[3];
    const float* node_emb  = (const float*)d_in[4];
    const float* edge_embs = (const float*)d_in[5];
    const float* Ws        = (const float*)d_in[6];
    const float* W_edges   = (const float*)d_in[7];
    const float* att_src   = (const float*)d_in[8];
    const float* att_dst   = (const float*)d_in[9];
    const float* att_edge  = (const float*)d_in[10];
    const float* biases    = (const float*)d_in[11];
    const float* W1        = (const float*)d_in[12];
    const float* b1        = (const float*)d_in[13];
    const float* W2        = (const float*)d_in[14];
    const float* b2        = (const float*)d_in[15];
    float* out = (float*)d_out;

    const int* src = edge_idx;
    const int* dst = edge_idx + NE;

    hist_pre_kernel<<<NE / 256 + 1, 256>>>(dst, edge_embs, W_edges, att_edge,
                                           node_emb, Ws, att_src, att_dst);
    scanfill_kernel<<<NBLK, 256>>>(x);
    scatter_kernel<<<(NE + 255) / 256, 256>>>(src, dst, edge_attr);

    agg_kernel<<<(NN * 32 + 255) / 256, 256>>>(0);   // launch #4 -> profiled
    for (int l = 1; l < LL; l++) {
        gemm_kernel<<<(NN + 63) / 64, 256>>>(l, Ws, att_src, att_dst, biases);
        agg_kernel<<<(NN * 32 + 255) / 256, 256>>>(l);
    }

    pool_kernel<<<(NN + 255) / 256, 256>>>(batch, biases);
    mlp_kernel<<<GG, 2 * D>>>(W1, b1, W2, b2, out);
}

// round 6
// speedup vs baseline: 1.8399x; 1.1056x over previous
#include <cuda_runtime.h>

#define NN 50000
#define NE 800000
#define D 64
#define LL 4
#define GG 128
#define TT 10
#define NEG_SLOPE 0.2f
#define EPSV 1e-16f
#define NBLK ((NN + 255) / 256)   // 196
#define NV 21                     // node vocab size

// ---------------- scratch (static __device__, zero-init at load) ----------------
__device__ int   g_deg[NN];        // zeroed by scatter_kernel at end of each run
__device__ int   g_rowptr[NN + 1];
__device__ int   g_cursor[NN];
__device__ unsigned g_epoch;                    // monotonic run counter
__device__ volatile unsigned g_aggflag[NBLK];   // epoch-tagged publish flags
__device__ volatile int      g_aggval[NBLK];
__device__ int   g_csr[NE];        // packed (attr<<24) | src
__device__ float g_alpha[NE];      // fallback path scratch
__device__ float g_hA[NN * D];
__device__ float g_hB[NN * D];
__device__ float g_gbuf[NN * D];
__device__ float g_asrc[NN];
__device__ float g_adst[NN];
__device__ float g_ewalpha[LL * 4];
__device__ float g_gt[NV * D];     // layer-0 g table
__device__ float g_ast[NV];        // layer-0 asrc table
__device__ float g_adt[NV];        // layer-0 adst table

// ---------------- hist + epoch + ewalpha + layer-0 table ----------------
__global__ void hist_pre_kernel(const int* __restrict__ dst,
                                const float* __restrict__ edge_embs,
                                const float* __restrict__ W_edges,
                                const float* __restrict__ att_edge,
                                const float* __restrict__ node_emb,
                                const float* __restrict__ Ws,
                                const float* __restrict__ att_src,
                                const float* __restrict__ att_dst) {
    int tid = threadIdx.x;
    int e = blockIdx.x * 256 + tid;
    if (e < NE) atomicAdd(&g_deg[dst[e]], 1);
    if (blockIdx.x == 0 && tid == 0) atomicAdd(&g_epoch, 1u);

    if (blockIdx.x == gridDim.x - 1) {
        __shared__ float sv[LL][D];
        __shared__ float sgt[NV][D];
        int l = tid >> 6, j = tid & 63;
        float v = 0.f;
        #pragma unroll
        for (int k = 0; k < D; k++)
            v += att_edge[l * D + k] * W_edges[l * D * D + k * D + j];
        sv[l][j] = v;
        int vg = tid >> 6;
        for (int vv = vg; vv < NV; vv += 4) {
            float acc = 0.f;
            #pragma unroll
            for (int k = 0; k < D; k++)
                acc = fmaf(node_emb[vv * D + k], Ws[j * D + k], acc);
            sgt[vv][j] = acc;
            g_gt[vv * D + j] = acc;
        }
        __syncthreads();
        if (tid < 16) {
            int ll = tid >> 2, a = tid & 3;
            float s = 0.f;
            for (int jj = 0; jj < D; jj++)
                s += edge_embs[ll * 4 * D + a * D + jj] * sv[ll][jj];
            g_ewalpha[ll * 4 + a] = s;
        }
        if (tid < NV) {
            float s = 0.f, dd = 0.f;
            #pragma unroll
            for (int jj = 0; jj < D; jj++) {
                s  += sgt[tid][jj] * att_src[jj];
                dd += sgt[tid][jj] * att_dst[jj];
            }
            g_ast[tid] = s;
            g_adt[tid] = dd;
        }
    }
}

// ---------------- single-kernel scan (publish + spin) + layer-0 fill ----------------
__global__ void scanfill_kernel(const int* __restrict__ x) {
    __shared__ int wsum[8];
    __shared__ int soffset;
    __shared__ __align__(16) float sgt[NV * D];
    int tid = threadIdx.x, lane = tid & 31, warp = tid >> 5;
    int b = blockIdx.x;
    unsigned epoch = g_epoch;

    int idx = b * 256 + tid;
    int v = (idx < NN) ? g_deg[idx] : 0;
    int xx = v;
    #pragma unroll
    for (int off = 1; off < 32; off <<= 1) {
        int t = __shfl_up_sync(0xFFFFFFFFu, xx, off);
        if (lane >= off) xx += t;
    }
    if (lane == 31) wsum[warp] = xx;
    __syncthreads();
    if (tid < 8) {
        int s = wsum[tid];
        #pragma unroll
        for (int off = 1; off < 8; off <<= 1) {
            int t = __shfl_up_sync(0xFFu, s, off);
            if (tid >= off) s += t;
        }
        wsum[tid] = s;
    }
    __syncthreads();
    int incl = xx + (warp ? wsum[warp - 1] : 0);

    if (tid == 255) {
        g_aggval[b] = incl;
        __threadfence();
        g_aggflag[b] = epoch;
    }
    if (warp == 0) {
        int sum = 0;
        for (int jj = lane; jj < b; jj += 32) {
            while (g_aggflag[jj] < epoch) { }
            sum += g_aggval[jj];
        }
        #pragma unroll
        for (int off = 16; off; off >>= 1)
            sum += __shfl_xor_sync(0xFFFFFFFFu, sum, off);
        if (lane == 0) soffset = sum;
    }
    __syncthreads();
    int r = incl + soffset;
    if (idx < NN) {
        g_rowptr[idx + 1] = r;
        g_cursor[idx] = r - v;
    }
    if (b == 0 && tid == 0) g_rowptr[0] = 0;

    // ---- layer-0 fill: gbuf/asrc/adst from tables ----
    for (int i = tid; i < NV * D; i += 256) sgt[i] = g_gt[i];
    __syncthreads();
    if (idx < NN) {
        int xv = x[idx];
        g_asrc[idx] = g_ast[xv];
        g_adst[idx] = g_adt[xv];
    }
    int nb = b * 256;
    for (int i = tid; i < 256 * 16; i += 256) {
        int nl = i >> 4, q = i & 15;
        int node = nb + nl;
        if (node < NN) {
            int xv = __ldg(&x[node]);
            ((float4*)g_gbuf)[node * 16 + q] = ((const float4*)sgt)[xv * 16 + q];
        }
    }
}

// ---------------- scatter (+ zero g_deg for next run) ----------------
__global__ void scatter_kernel(const int* __restrict__ src,
                               const int* __restrict__ dst,
                               const int* __restrict__ attr) {
    int e = blockIdx.x * blockDim.x + threadIdx.x;
    if (e < NE) {
        int pos = atomicAdd(&g_cursor[dst[e]], 1);
        g_csr[pos] = (attr[e] << 24) | src[e];
    }
    if (e < NN) g_deg[e] = 0;
}

// ---------------- per-layer node GEMM (layers 1..3): 4x4 register-tiled ----------------
__global__ void __launch_bounds__(256) gemm_kernel(
        int layer,
        const float* __restrict__ Ws,
        const float* __restrict__ att_src,
        const float* __restrict__ att_dst,
        const float* __restrict__ biases) {
    __shared__ __align__(16) float shT[64][68];
    __shared__ __align__(16) float sWT[64][68];
    __shared__ float sred[2][16][64];

    const float* W = Ws + layer * D * D;
    const float* in_h = (((layer - 1) & 1) == 0) ? g_hA : g_hB;
    const float* bias = biases + (layer - 1) * D;
    const float* a_s = att_src + layer * D;
    const float* a_d = att_dst + layer * D;

    int tid = threadIdx.x;
    int nb = blockIdx.x * 64;

    for (int idx = tid; idx < D * D; idx += 256) {
        sWT[idx & 63][idx >> 6] = W[idx];
    }
    for (int idx = tid; idx < 64 * D; idx += 256) {
        int nl = idx >> 6, k = idx & 63;
        int node = nb + nl;
        float hv = 0.f;
        if (node < NN)
            hv = fmaxf(in_h[node * D + k] + bias[k], 0.f);
        shT[k][nl] = hv;
    }
    __syncthreads();

    int tx = tid & 15;
    int ty = tid >> 4;
    int n0 = tx * 4;
    int j0 = ty * 4;

    float acc[4][4] = {};
    #pragma unroll 8
    for (int k = 0; k < 64; k++) {
        float4 hv = *(const float4*)&shT[k][n0];
        float4 wv = *(const float4*)&sWT[k][j0];
        acc[0][0] = fmaf(hv.x, wv.x, acc[0][0]);
        acc[0][1] = fmaf(hv.x, wv.y, acc[0][1]);
        acc[0][2] = fmaf(hv.x, wv.z, acc[0][2]);
        acc[0][3] = fmaf(hv.x, wv.w, acc[0][3]);
        acc[1][0] = fmaf(hv.y, wv.x, acc[1][0]);
        acc[1][1] = fmaf(hv.y, wv.y, acc[1][1]);
        acc[1][2] = fmaf(hv.y, wv.z, acc[1][2]);
        acc[1][3] = fmaf(hv.y, wv.w, acc[1][3]);
        acc[2][0] = fmaf(hv.z, wv.x, acc[2][0]);
        acc[2][1] = fmaf(hv.z, wv.y, acc[2][1]);
        acc[2][2] = fmaf(hv.z, wv.z, acc[2][2]);
        acc[2][3] = fmaf(hv.z, wv.w, acc[2][3]);
        acc[3][0] = fmaf(hv.w, wv.x, acc[3][0]);
        acc[3][1] = fmaf(hv.w, wv.y, acc[3][1]);
        acc[3][2] = fmaf(hv.w, wv.z, acc[3][2]);
        acc[3][3] = fmaf(hv.w, wv.w, acc[3][3]);
    }

    float as0 = a_s[j0], as1 = a_s[j0 + 1], as2 = a_s[j0 + 2], as3 = a_s[j0 + 3];
    float ad0 = a_d[j0], ad1 = a_d[j0 + 1], ad2 = a_d[j0 + 2], ad3 = a_d[j0 + 3];
    #pragma unroll
    for (int i = 0; i < 4; i++) {
        float sa = acc[i][0] * as0 + acc[i][1] * as1 + acc[i][2] * as2 + acc[i][3] * as3;
        float sd = acc[i][0] * ad0 + acc[i][1] * ad1 + acc[i][2] * ad2 + acc[i][3] * ad3;
        sred[0][ty][n0 + i] = sa;
        sred[1][ty][n0 + i] = sd;
        int node = nb + n0 + i;
        if (node < NN) {
            *(float4*)&g_gbuf[node * D + j0] =
                make_float4(acc[i][0], acc[i][1], acc[i][2], acc[i][3]);
        }
    }
    __syncthreads();
    if (tid < 64) {
        float s = 0.f, dsum = 0.f;
        #pragma unroll
        for (int t = 0; t < 16; t++) {
            s    += sred[0][t][tid];
            dsum += sred[1][t][tid];
        }
        int node = nb + tid;
        if (node < NN) { g_asrc[node] = s; g_adst[node] = dsum; }
    }
}

// ---------------- aggregation: warp/node; deg-tiered ----------------
__global__ void agg_kernel(int layer) {
    const unsigned F = 0xFFFFFFFFu;
    int gwarp = (blockIdx.x * blockDim.x + threadIdx.x) >> 5;
    int lane = threadIdx.x & 31;
    if (gwarp >= NN) return;
    int n = gwarp;

    const float* ewa = g_ewalpha + layer * 4;
    float* out_h = ((layer & 1) == 0) ? g_hA : g_hB;

    int start = g_rowptr[n];
    int end   = g_rowptr[n + 1];
    int deg   = end - start;

    int half  = lane >> 4;        // 0: even edges, 1: odd edges
    int qlane = lane & 15;        // float4 column group
    const float* gb = g_gbuf + (qlane << 2);
    float4 acc4 = make_float4(0.f, 0.f, 0.f, 0.f);

    if (deg == 0) {
        if (half == 0)
            *(float4*)(out_h + n * D + (qlane << 2)) = acc4;
        return;
    }

    float adst_n = g_adst[n];

    if (deg <= 32) {
        // -------- dominant path: one edge per lane --------
        int p = 0;
        float a = -1e30f;
        if (lane < deg) {
            p = __ldg(&g_csr[start + lane]);
            a = g_asrc[p & 0x00FFFFFF] + adst_n + ewa[p >> 24];
            a = (a > 0.f) ? a : NEG_SLOPE * a;
        }
        float m = a;
        #pragma unroll
        for (int off = 16; off; off >>= 1)
            m = fmaxf(m, __shfl_xor_sync(F, m, off));
        float ex = __expf(a - m);          // invalid lanes -> exp(-inf)=0
        float s = ex;
        #pragma unroll
        for (int off = 16; off; off >>= 1)
            s += __shfl_xor_sync(F, s, off);
        float w = ex * (1.f / (s + EPSV)); // invalid lanes: w = 0
        int sv = p & 0x00FFFFFF;

        // gather: 4 rows in flight (2 per half-warp)
        int t = 0;
        for (; t + 4 <= deg; t += 4) {
            float w0 = __shfl_sync(F, w,  t + half);
            int   s0 = __shfl_sync(F, sv, t + half);
            float w1 = __shfl_sync(F, w,  t + 2 + half);
            int   s1 = __shfl_sync(F, sv, t + 2 + half);
            float4 v0 = *(const float4*)(gb + s0 * D);
            float4 v1 = *(const float4*)(gb + s1 * D);
            acc4.x = fmaf(w0, v0.x, acc4.x);
            acc4.y = fmaf(w0, v0.y, acc4.y);
            acc4.z = fmaf(w0, v0.z, acc4.z);
            acc4.w = fmaf(w0, v0.w, acc4.w);
            acc4.x = fmaf(w1, v1.x, acc4.x);
            acc4.y = fmaf(w1, v1.y, acc4.y);
            acc4.z = fmaf(w1, v1.z, acc4.z);
            acc4.w = fmaf(w1, v1.w, acc4.w);
        }
        for (; t < deg; t += 2) {
            // e = t+half <= deg <= 32-1 guaranteed (t even, t<deg); lanes with
            // e >= deg broadcast w=0 so their contribution vanishes.
            float w0 = __shfl_sync(F, w,  (t + half) & 31);
            int   s0 = __shfl_sync(F, sv, (t + half) & 31);
            float4 v0 = *(const float4*)(gb + s0 * D);
            acc4.x = fmaf(w0, v0.x, acc4.x);
            acc4.y = fmaf(w0, v0.y, acc4.y);
            acc4.z = fmaf(w0, v0.z, acc4.z);
            acc4.w = fmaf(w0, v0.w, acc4.w);
        }
    } else if (deg <= 128) {
        // -------- medium path: register-resident, 4 per lane --------
        int   srcs[4];
        float av[4];
        float m = -1e30f;
        #pragma unroll
        for (int i = 0; i < 4; i++) {
            int e = start + lane + 32 * i;
            if (e < end) {
                int p = __ldg(&g_csr[e]);
                srcs[i] = p & 0x00FFFFFF;
                float a = g_asrc[srcs[i]] + adst_n + ewa[p >> 24];
                a = (a > 0.f) ? a : NEG_SLOPE * a;
                av[i] = a;
                m = fmaxf(m, a);
            } else { srcs[i] = 0; av[i] = -1e30f; }
        }
        #pragma unroll
        for (int off = 16; off; off >>= 1)
            m = fmaxf(m, __shfl_xor_sync(F, m, off));

        float s = 0.f;
        #pragma unroll
        for (int i = 0; i < 4; i++) {
            av[i] = __expf(av[i] - m);
            s += av[i];
        }
        #pragma unroll
        for (int off = 16; off; off >>= 1)
            s += __shfl_xor_sync(F, s, off);
        float inv = 1.f / (s + EPSV);

        #pragma unroll
        for (int i = 0; i < 4; i++) {
            if (32 * i >= deg) break;
            int cnt = min(32, deg - 32 * i);
            float w = av[i] * inv;
            int   sv = srcs[i];
            for (int t = 0; t < cnt; t += 2) {
                float w0 = __shfl_sync(F, w,  (t + half) & 31);
                int   s0 = __shfl_sync(F, sv, (t + half) & 31);
                float4 v0 = *(const float4*)(gb + s0 * D);
                acc4.x = fmaf(w0, v0.x, acc4.x);
                acc4.y = fmaf(w0, v0.y, acc4.y);
                acc4.z = fmaf(w0, v0.z, acc4.z);
                acc4.w = fmaf(w0, v0.w, acc4.w);
            }
        }
    } else {
        // -------- fallback: 3 passes via g_alpha --------
        float m = -1e30f;
        for (int e = start + lane; e < end; e += 32) {
            int p = g_csr[e];
            float a = g_asrc[p & 0x00FFFFFF] + adst_n + ewa[p >> 24];
            a = (a > 0.f) ? a : NEG_SLOPE * a;
            g_alpha[e] = a;
            m = fmaxf(m, a);
        }
        #pragma unroll
        for (int off = 16; off; off >>= 1)
            m = fmaxf(m, __shfl_xor_sync(F, m, off));
        float s = 0.f;
        for (int e = start + lane; e < end; e += 32) {
            float ex = __expf(g_alpha[e] - m);
            g_alpha[e] = ex;
            s += ex;
        }
        #pragma unroll
        for (int off = 16; off; off >>= 1)
            s += __shfl_xor_sync(F, s, off);
        float inv = 1.f / (s + EPSV);

        for (int base = start; base < end; base += 32) {
            int cnt = min(32, end - base);
            float w = 0.f; int sv = 0;
            if (lane < cnt) {
                int p = g_csr[base + lane];
                sv = p & 0x00FFFFFF;
                w = g_alpha[base + lane] * inv;
            }
            for (int t = 0; t < cnt; t += 2) {
                float w0 = __shfl_sync(F, w,  (t + half) & 31);
                int   s0 = __shfl_sync(F, sv, (t + half) & 31);
                float4 v0 = *(const float4*)(gb + s0 * D);
                acc4.x = fmaf(w0, v0.x, acc4.x);
                acc4.y = fmaf(w0, v0.y, acc4.y);
                acc4.z = fmaf(w0, v0.z, acc4.z);
                acc4.w = fmaf(w0, v0.w, acc4.w);
            }
        }
    }

    acc4.x += __shfl_xor_sync(F, acc4.x, 16);
    acc4.y += __shfl_xor_sync(F, acc4.y, 16);
    acc4.z += __shfl_xor_sync(F, acc4.z, 16);
    acc4.w += __shfl_xor_sync(F, acc4.w, 16);
    if (half == 0)
        *(float4*)(out_h + n * D + (qlane << 2)) = acc4;
}

// ---------------- fused pooling + MLP: one block per graph ----------------
__global__ void __launch_bounds__(256) poolmlp_kernel(
        const int* __restrict__ batch,
        const float* __restrict__ biases,
        const float* __restrict__ W1, const float* __restrict__ b1,
        const float* __restrict__ W2, const float* __restrict__ b2,
        float* __restrict__ out) {
    __shared__ float sacc[4][D];
    __shared__ float sp[D];
    __shared__ float shid[2 * D];
    int g = blockIdx.x;
    int tid = threadIdx.x;   // 256

    // node range of graph g via binary search on sorted batch
    int lo = 0, hi = NN;
    while (lo < hi) { int mid = (lo + hi) >> 1; if (batch[mid] < g) lo = mid + 1; else hi = mid; }
    int startn = lo;
    hi = NN;
    while (lo < hi) { int mid = (lo + hi) >> 1; if (batch[mid] <= g) lo = mid + 1; else hi = mid; }
    int endn = lo;

    int j = tid & 63, rg = tid >> 6;
    float bj = biases[3 * D + j];
    float acc = 0.f;
    for (int nn = startn + rg; nn < endn; nn += 4)
        acc += fmaxf(g_hB[nn * D + j] + bj, 0.f);
    sacc[rg][j] = acc;
    __syncthreads();
    if (tid < D)
        sp[tid] = sacc[0][tid] + sacc[1][tid] + sacc[2][tid] + sacc[3][tid];
    __syncthreads();
    if (tid < 2 * D) {
        float hsum = b1[tid];
        #pragma unroll
        for (int k = 0; k < D; k++)
            hsum = fmaf(sp[k], W1[tid * D + k], hsum);
        shid[tid] = fmaxf(hsum, 0.f);
    }
    __syncthreads();
    if (tid < TT) {
        float o = b2[tid];
        #pragma unroll
        for (int k = 0; k < 2 * D; k++)
            o = fmaf(shid[k], W2[tid * 2 * D + k], o);
        out[g * TT + tid] = o;
    }
}

// ---------------- launch ----------------
extern "C" void kernel_launch(void* const* d_in, const int* in_sizes, int n_in,
                              void* d_out, int out_size) {
    const int*   x         = (const int*)  d_in[0];
    const int*   edge_idx  = (const int*)  d_in[1];
    const int*   edge_attr = (const int*)  d_in[2];
    const int*   batch     = (const int*)  d_in[3];
    const float* node_emb  = (const float*)d_in[4];
    const float* edge_embs = (const float*)d_in[5];
    const float* Ws        = (const float*)d_in[6];
    const float* W_edges   = (const float*)d_in[7];
    const float* att_src   = (const float*)d_in[8];
    const float* att_dst   = (const float*)d_in[9];
    const float* att_edge  = (const float*)d_in[10];
    const float* biases    = (const float*)d_in[11];
    const float* W1        = (const float*)d_in[12];
    const float* b1        = (const float*)d_in[13];
    const float* W2        = (const float*)d_in[14];
    const float* b2        = (const float*)d_in[15];
    float* out = (float*)d_out;

    const int* src = edge_idx;
    const int* dst = edge_idx + NE;

    hist_pre_kernel<<<NE / 256 + 1, 256>>>(dst, edge_embs, W_edges, att_edge,
                                           node_emb, Ws, att_src, att_dst);
    scanfill_kernel<<<NBLK, 256>>>(x);
    scatter_kernel<<<(NE + 255) / 256, 256>>>(src, dst, edge_attr);

    agg_kernel<<<(NN * 32 + 255) / 256, 256>>>(0);   // launch #4 -> profiled
    for (int l = 1; l < LL; l++) {
        gemm_kernel<<<(NN + 63) / 64, 256>>>(l, Ws, att_src, att_dst, biases);
        agg_kernel<<<(NN * 32 + 255) / 256, 256>>>(l);
    }

    poolmlp_kernel<<<GG, 256>>>(batch, biases, W1, b1, W2, b2, out);
}

// round 7
// speedup vs baseline: 1.9293x; 1.0486x over previous
#include <cuda_runtime.h>

#define NN 50000
#define NE 800000
#define D 64
#define LL 4
#define GG 128
#define TT 10
#define NEG_SLOPE 0.2f
#define EPSV 1e-16f
#define NBLK ((NN + 255) / 256)   // 196
#define NV 21                     // node vocab size

// ---------------- scratch (static __device__, zero-init at load) ----------------
__device__ int   g_deg[NN];        // zeroed by scatter_kernel at end of each run
__device__ int   g_rowptr[NN + 1];
__device__ int   g_cursor[NN];
__device__ unsigned g_epoch;                    // monotonic run counter
__device__ volatile unsigned g_aggflag[NBLK];   // epoch-tagged publish flags
__device__ volatile int      g_aggval[NBLK];
__device__ int   g_csr[NE];        // packed (attr<<24) | src
__device__ float g_alpha[NE];      // fallback path scratch
__device__ float g_hA[NN * D];
__device__ float g_hB[NN * D];
__device__ float g_gbuf[NN * D];
__device__ float g_asrc[NN];
__device__ float g_adst[NN];
__device__ float g_ewalpha[LL * 4];
__device__ float g_gt[NV * D];     // layer-0 g table
__device__ float g_ast[NV];        // layer-0 asrc table
__device__ float g_adt[NV];        // layer-0 adst table

// ---------------- hist + epoch + ewalpha + layer-0 table ----------------
__global__ void hist_pre_kernel(const int* __restrict__ dst,
                                const float* __restrict__ edge_embs,
                                const float* __restrict__ W_edges,
                                const float* __restrict__ att_edge,
                                const float* __restrict__ node_emb,
                                const float* __restrict__ Ws,
                                const float* __restrict__ att_src,
                                const float* __restrict__ att_dst) {
    int tid = threadIdx.x;
    int e = blockIdx.x * 256 + tid;
    if (e < NE) atomicAdd(&g_deg[dst[e]], 1);
    if (blockIdx.x == 0 && tid == 0) atomicAdd(&g_epoch, 1u);

    if (blockIdx.x == gridDim.x - 1) {
        __shared__ float sv[LL][D];
        __shared__ float sgt[NV][D];
        int l = tid >> 6, j = tid & 63;
        float v = 0.f;
        #pragma unroll
        for (int k = 0; k < D; k++)
            v += att_edge[l * D + k] * W_edges[l * D * D + k * D + j];
        sv[l][j] = v;
        int vg = tid >> 6;
        for (int vv = vg; vv < NV; vv += 4) {
            float acc = 0.f;
            #pragma unroll
            for (int k = 0; k < D; k++)
                acc = fmaf(node_emb[vv * D + k], Ws[j * D + k], acc);
            sgt[vv][j] = acc;
            g_gt[vv * D + j] = acc;
        }
        __syncthreads();
        if (tid < 16) {
            int ll = tid >> 2, a = tid & 3;
            float s = 0.f;
            for (int jj = 0; jj < D; jj++)
                s += edge_embs[ll * 4 * D + a * D + jj] * sv[ll][jj];
            g_ewalpha[ll * 4 + a] = s;
        }
        if (tid < NV) {
            float s = 0.f, dd = 0.f;
            #pragma unroll
            for (int jj = 0; jj < D; jj++) {
                s  += sgt[tid][jj] * att_src[jj];
                dd += sgt[tid][jj] * att_dst[jj];
            }
            g_ast[tid] = s;
            g_adt[tid] = dd;
        }
    }
}

// ---------------- single-kernel scan (publish + spin) + layer-0 fill ----------------
__global__ void scanfill_kernel(const int* __restrict__ x) {
    __shared__ int wsum[8];
    __shared__ int soffset;
    __shared__ __align__(16) float sgt[NV * D];
    int tid = threadIdx.x, lane = tid & 31, warp = tid >> 5;
    int b = blockIdx.x;
    unsigned epoch = g_epoch;

    int idx = b * 256 + tid;
    int v = (idx < NN) ? g_deg[idx] : 0;
    int xx = v;
    #pragma unroll
    for (int off = 1; off < 32; off <<= 1) {
        int t = __shfl_up_sync(0xFFFFFFFFu, xx, off);
        if (lane >= off) xx += t;
    }
    if (lane == 31) wsum[warp] = xx;
    __syncthreads();
    if (tid < 8) {
        int s = wsum[tid];
        #pragma unroll
        for (int off = 1; off < 8; off <<= 1) {
            int t = __shfl_up_sync(0xFFu, s, off);
            if (tid >= off) s += t;
        }
        wsum[tid] = s;
    }
    __syncthreads();
    int incl = xx + (warp ? wsum[warp - 1] : 0);

    if (tid == 255) {
        g_aggval[b] = incl;
        __threadfence();
        g_aggflag[b] = epoch;
    }
    if (warp == 0) {
        int sum = 0;
        for (int jj = lane; jj < b; jj += 32) {
            while (g_aggflag[jj] < epoch) { }
            sum += g_aggval[jj];
        }
        #pragma unroll
        for (int off = 16; off; off >>= 1)
            sum += __shfl_xor_sync(0xFFFFFFFFu, sum, off);
        if (lane == 0) soffset = sum;
    }
    __syncthreads();
    int r = incl + soffset;
    if (idx < NN) {
        g_rowptr[idx + 1] = r;
        g_cursor[idx] = r - v;
    }
    if (b == 0 && tid == 0) g_rowptr[0] = 0;

    // ---- layer-0 fill: gbuf/asrc/adst from tables ----
    for (int i = tid; i < NV * D; i += 256) sgt[i] = g_gt[i];
    __syncthreads();
    if (idx < NN) {
        int xv = x[idx];
        g_asrc[idx] = g_ast[xv];
        g_adst[idx] = g_adt[xv];
    }
    int nb = b * 256;
    for (int i = tid; i < 256 * 16; i += 256) {
        int nl = i >> 4, q = i & 15;
        int node = nb + nl;
        if (node < NN) {
            int xv = __ldg(&x[node]);
            ((float4*)g_gbuf)[node * 16 + q] = ((const float4*)sgt)[xv * 16 + q];
        }
    }
}

// ---------------- scatter (+ zero g_deg for next run) ----------------
__global__ void scatter_kernel(const int* __restrict__ src,
                               const int* __restrict__ dst,
                               const int* __restrict__ attr) {
    int e = blockIdx.x * blockDim.x + threadIdx.x;
    if (e < NE) {
        int pos = atomicAdd(&g_cursor[dst[e]], 1);
        g_csr[pos] = (attr[e] << 24) | src[e];
    }
    if (e < NN) g_deg[e] = 0;
}

// ---------------- per-layer node GEMM (layers 1..3): 4x4 register-tiled ----------------
__global__ void __launch_bounds__(256) gemm_kernel(
        int layer,
        const float* __restrict__ Ws,
        const float* __restrict__ att_src,
        const float* __restrict__ att_dst,
        const float* __restrict__ biases) {
    __shared__ __align__(16) float shT[64][68];
    __shared__ __align__(16) float sWT[64][68];
    __shared__ float sred[2][16][64];

    const float* W = Ws + layer * D * D;
    const float* in_h = (((layer - 1) & 1) == 0) ? g_hA : g_hB;
    const float* bias = biases + (layer - 1) * D;
    const float* a_s = att_src + layer * D;
    const float* a_d = att_dst + layer * D;

    int tid = threadIdx.x;
    int nb = blockIdx.x * 64;

    for (int idx = tid; idx < D * D; idx += 256) {
        sWT[idx & 63][idx >> 6] = W[idx];
    }
    for (int idx = tid; idx < 64 * D; idx += 256) {
        int nl = idx >> 6, k = idx & 63;
        int node = nb + nl;
        float hv = 0.f;
        if (node < NN)
            hv = fmaxf(in_h[node * D + k] + bias[k], 0.f);
        shT[k][nl] = hv;
    }
    __syncthreads();

    int tx = tid & 15;
    int ty = tid >> 4;
    int n0 = tx * 4;
    int j0 = ty * 4;

    float acc[4][4] = {};
    #pragma unroll 8
    for (int k = 0; k < 64; k++) {
        float4 hv = *(const float4*)&shT[k][n0];
        float4 wv = *(const float4*)&sWT[k][j0];
        acc[0][0] = fmaf(hv.x, wv.x, acc[0][0]);
        acc[0][1] = fmaf(hv.x, wv.y, acc[0][1]);
        acc[0][2] = fmaf(hv.x, wv.z, acc[0][2]);
        acc[0][3] = fmaf(hv.x, wv.w, acc[0][3]);
        acc[1][0] = fmaf(hv.y, wv.x, acc[1][0]);
        acc[1][1] = fmaf(hv.y, wv.y, acc[1][1]);
        acc[1][2] = fmaf(hv.y, wv.z, acc[1][2]);
        acc[1][3] = fmaf(hv.y, wv.w, acc[1][3]);
        acc[2][0] = fmaf(hv.z, wv.x, acc[2][0]);
        acc[2][1] = fmaf(hv.z, wv.y, acc[2][1]);
        acc[2][2] = fmaf(hv.z, wv.z, acc[2][2]);
        acc[2][3] = fmaf(hv.z, wv.w, acc[2][3]);
        acc[3][0] = fmaf(hv.w, wv.x, acc[3][0]);
        acc[3][1] = fmaf(hv.w, wv.y, acc[3][1]);
        acc[3][2] = fmaf(hv.w, wv.z, acc[3][2]);
        acc[3][3] = fmaf(hv.w, wv.w, acc[3][3]);
    }

    float as0 = a_s[j0], as1 = a_s[j0 + 1], as2 = a_s[j0 + 2], as3 = a_s[j0 + 3];
    float ad0 = a_d[j0], ad1 = a_d[j0 + 1], ad2 = a_d[j0 + 2], ad3 = a_d[j0 + 3];
    #pragma unroll
    for (int i = 0; i < 4; i++) {
        float sa = acc[i][0] * as0 + acc[i][1] * as1 + acc[i][2] * as2 + acc[i][3] * as3;
        float sd = acc[i][0] * ad0 + acc[i][1] * ad1 + acc[i][2] * ad2 + acc[i][3] * ad3;
        sred[0][ty][n0 + i] = sa;
        sred[1][ty][n0 + i] = sd;
        int node = nb + n0 + i;
        if (node < NN) {
            *(float4*)&g_gbuf[node * D + j0] =
                make_float4(acc[i][0], acc[i][1], acc[i][2], acc[i][3]);
        }
    }
    __syncthreads();
    if (tid < 64) {
        float s = 0.f, dsum = 0.f;
        #pragma unroll
        for (int t = 0; t < 16; t++) {
            s    += sred[0][t][tid];
            dsum += sred[1][t][tid];
        }
        int node = nb + tid;
        if (node < NN) { g_asrc[node] = s; g_adst[node] = dsum; }
    }
}

// ---------------- aggregation: warp/node; deg-tiered; 8-edge-unrolled gather ----------------
__global__ void __launch_bounds__(128) agg_kernel(int layer) {
    const unsigned F = 0xFFFFFFFFu;
    int gwarp = (blockIdx.x * blockDim.x + threadIdx.x) >> 5;
    int lane = threadIdx.x & 31;
    if (gwarp >= NN) return;
    int n = gwarp;

    const float* ewa = g_ewalpha + layer * 4;
    float* out_h = ((layer & 1) == 0) ? g_hA : g_hB;

    int start = g_rowptr[n];
    int end   = g_rowptr[n + 1];
    int deg   = end - start;

    int half  = lane >> 4;        // 0: even edges, 1: odd edges
    int qlane = lane & 15;        // float4 column group
    const float* gb = g_gbuf + (qlane << 2);
    float4 acc4 = make_float4(0.f, 0.f, 0.f, 0.f);

    if (deg == 0) {
        if (half == 0)
            *(float4*)(out_h + n * D + (qlane << 2)) = acc4;
        return;
    }

    float adst_n = g_adst[n];

    if (deg <= 32) {
        // -------- dominant path: one edge per lane --------
        int p = 0;
        float a = -1e30f;
        if (lane < deg) {
            p = __ldg(&g_csr[start + lane]);
            a = g_asrc[p & 0x00FFFFFF] + adst_n + ewa[p >> 24];
            a = (a > 0.f) ? a : NEG_SLOPE * a;
        }
        float m = a;
        #pragma unroll
        for (int off = 16; off; off >>= 1)
            m = fmaxf(m, __shfl_xor_sync(F, m, off));
        float ex = __expf(a - m);          // invalid lanes -> exp(-inf)=0
        float s = ex;
        #pragma unroll
        for (int off = 16; off; off >>= 1)
            s += __shfl_xor_sync(F, s, off);
        float w = ex * (1.f / (s + EPSV)); // invalid lanes: w = 0
        int sv = p & 0x00FFFFFF;

        // gather: 8 edges per iteration (4 per half-warp, 4 loads in flight).
        // trip count rounded up: padded lanes broadcast w=0, sv=0 (harmless).
        for (int t = 0; t < deg; t += 8) {
            int e0 = (t     + half) & 31;
            int e1 = (t + 2 + half) & 31;
            int e2 = (t + 4 + half) & 31;
            int e3 = (t + 6 + half) & 31;
            float w0 = __shfl_sync(F, w, e0);  int s0 = __shfl_sync(F, sv, e0);
            float w1 = __shfl_sync(F, w, e1);  int s1 = __shfl_sync(F, sv, e1);
            float w2 = __shfl_sync(F, w, e2);  int s2 = __shfl_sync(F, sv, e2);
            float w3 = __shfl_sync(F, w, e3);  int s3 = __shfl_sync(F, sv, e3);
            float4 v0 = *(const float4*)(gb + s0 * D);
            float4 v1 = *(const float4*)(gb + s1 * D);
            float4 v2 = *(const float4*)(gb + s2 * D);
            float4 v3 = *(const float4*)(gb + s3 * D);
            acc4.x = fmaf(w0, v0.x, acc4.x);
            acc4.y = fmaf(w0, v0.y, acc4.y);
            acc4.z = fmaf(w0, v0.z, acc4.z);
            acc4.w = fmaf(w0, v0.w, acc4.w);
            acc4.x = fmaf(w1, v1.x, acc4.x);
            acc4.y = fmaf(w1, v1.y, acc4.y);
            acc4.z = fmaf(w1, v1.z, acc4.z);
            acc4.w = fmaf(w1, v1.w, acc4.w);
            acc4.x = fmaf(w2, v2.x, acc4.x);
            acc4.y = fmaf(w2, v2.y, acc4.y);
            acc4.z = fmaf(w2, v2.z, acc4.z);
            acc4.w = fmaf(w2, v2.w, acc4.w);
            acc4.x = fmaf(w3, v3.x, acc4.x);
            acc4.y = fmaf(w3, v3.y, acc4.y);
            acc4.z = fmaf(w3, v3.z, acc4.z);
            acc4.w = fmaf(w3, v3.w, acc4.w);
        }
    } else if (deg <= 128) {
        // -------- medium path: register-resident, 4 per lane --------
        int   srcs[4];
        float av[4];
        float m = -1e30f;
        #pragma unroll
        for (int i = 0; i < 4; i++) {
            int e = start + lane + 32 * i;
            if (e < end) {
                int p = __ldg(&g_csr[e]);
                srcs[i] = p & 0x00FFFFFF;
                float a = g_asrc[srcs[i]] + adst_n + ewa[p >> 24];
                a = (a > 0.f) ? a : NEG_SLOPE * a;
                av[i] = a;
                m = fmaxf(m, a);
            } else { srcs[i] = 0; av[i] = -1e30f; }
        }
        #pragma unroll
        for (int off = 16; off; off >>= 1)
            m = fmaxf(m, __shfl_xor_sync(F, m, off));

        float s = 0.f;
        #pragma unroll
        for (int i = 0; i < 4; i++) {
            av[i] = __expf(av[i] - m);
            s += av[i];
        }
        #pragma unroll
        for (int off = 16; off; off >>= 1)
            s += __shfl_xor_sync(F, s, off);
        float inv = 1.f / (s + EPSV);

        #pragma unroll
        for (int i = 0; i < 4; i++) {
            if (32 * i >= deg) break;
            int cnt = min(32, deg - 32 * i);
            float w = av[i] * inv;
            int   sv = srcs[i];
            for (int t = 0; t < cnt; t += 2) {
                float w0 = __shfl_sync(F, w,  (t + half) & 31);
                int   s0 = __shfl_sync(F, sv, (t + half) & 31);
                float4 v0 = *(const float4*)(gb + s0 * D);
                acc4.x = fmaf(w0, v0.x, acc4.x);
                acc4.y = fmaf(w0, v0.y, acc4.y);
                acc4.z = fmaf(w0, v0.z, acc4.z);
                acc4.w = fmaf(w0, v0.w, acc4.w);
            }
        }
    } else {
        // -------- fallback: 3 passes via g_alpha --------
        float m = -1e30f;
        for (int e = start + lane; e < end; e += 32) {
            int p = g_csr[e];
            float a = g_asrc[p & 0x00FFFFFF] + adst_n + ewa[p >> 24];
            a = (a > 0.f) ? a : NEG_SLOPE * a;
            g_alpha[e] = a;
            m = fmaxf(m, a);
        }
        #pragma unroll
        for (int off = 16; off; off >>= 1)
            m = fmaxf(m, __shfl_xor_sync(F, m, off));
        float s = 0.f;
        for (int e = start + lane; e < end; e += 32) {
            float ex = __expf(g_alpha[e] - m);
            g_alpha[e] = ex;
            s += ex;
        }
        #pragma unroll
        for (int off = 16; off; off >>= 1)
            s += __shfl_xor_sync(F, s, off);
        float inv = 1.f / (s + EPSV);

        for (int base = start; base < end; base += 32) {
            int cnt = min(32, end - base);
            float w = 0.f; int sv = 0;
            if (lane < cnt) {
                int p = g_csr[base + lane];
                sv = p & 0x00FFFFFF;
                w = g_alpha[base + lane] * inv;
            }
            for (int t = 0; t < cnt; t += 2) {
                float w0 = __shfl_sync(F, w,  (t + half) & 31);
                int   s0 = __shfl_sync(F, sv, (t + half) & 31);
                float4 v0 = *(const float4*)(gb + s0 * D);
                acc4.x = fmaf(w0, v0.x, acc4.x);
                acc4.y = fmaf(w0, v0.y, acc4.y);
                acc4.z = fmaf(w0, v0.z, acc4.z);
                acc4.w = fmaf(w0, v0.w, acc4.w);
            }
        }
    }

    acc4.x += __shfl_xor_sync(F, acc4.x, 16);
    acc4.y += __shfl_xor_sync(F, acc4.y, 16);
    acc4.z += __shfl_xor_sync(F, acc4.z, 16);
    acc4.w += __shfl_xor_sync(F, acc4.w, 16);
    if (half == 0)
        *(float4*)(out_h + n * D + (qlane << 2)) = acc4;
}

// ---------------- fused pooling + MLP: one block per graph ----------------
__global__ void __launch_bounds__(256) poolmlp_kernel(
        const int* __restrict__ batch,
        const float* __restrict__ biases,
        const float* __restrict__ W1, const float* __restrict__ b1,
        const float* __restrict__ W2, const float* __restrict__ b2,
        float* __restrict__ out) {
    __shared__ float sacc[4][D];
    __shared__ float sp[D];
    __shared__ float shid[2 * D];
    int g = blockIdx.x;
    int tid = threadIdx.x;   // 256

    int lo = 0, hi = NN;
    while (lo < hi) { int mid = (lo + hi) >> 1; if (batch[mid] < g) lo = mid + 1; else hi = mid; }
    int startn = lo;
    hi = NN;
    while (lo < hi) { int mid = (lo + hi) >> 1; if (batch[mid] <= g) lo = mid + 1; else hi = mid; }
    int endn = lo;

    int j = tid & 63, rg = tid >> 6;
    float bj = biases[3 * D + j];
    float acc = 0.f;
    for (int nn = startn + rg; nn < endn; nn += 4)
        acc += fmaxf(g_hB[nn * D + j] + bj, 0.f);
    sacc[rg][j] = acc;
    __syncthreads();
    if (tid < D)
        sp[tid] = sacc[0][tid] + sacc[1][tid] + sacc[2][tid] + sacc[3][tid];
    __syncthreads();
    if (tid < 2 * D) {
        float hsum = b1[tid];
        #pragma unroll
        for (int k = 0; k < D; k++)
            hsum = fmaf(sp[k], W1[tid * D + k], hsum);
        shid[tid] = fmaxf(hsum, 0.f);
    }
    __syncthreads();
    if (tid < TT) {
        float o = b2[tid];
        #pragma unroll
        for (int k = 0; k < 2 * D; k++)
            o = fmaf(shid[k], W2[tid * 2 * D + k], o);
        out[g * TT + tid] = o;
    }
}

// ---------------- launch ----------------
extern "C" void kernel_launch(void* const* d_in, const int* in_sizes, int n_in,
                              void* d_out, int out_size) {
    const int*   x         = (const int*)  d_in[0];
    const int*   edge_idx  = (const int*)  d_in[1];
    const int*   edge_attr = (const int*)  d_in[2];
    const int*   batch     = (const int*)  d_in[3];
    const float* node_emb  = (const float*)d_in[4];
    const float* edge_embs = (const float*)d_in[5];
    const float* Ws        = (const float*)d_in[6];
    const float* W_edges   = (const float*)d_in[7];
    const float* att_src   = (const float*)d_in[8];
    const float* att_dst   = (const float*)d_in[9];
    const float* att_edge  = (const float*)d_in[10];
    const float* biases    = (const float*)d_in[11];
    const float* W1        = (const float*)d_in[12];
    const float* b1        = (const float*)d_in[13];
    const float* W2        = (const float*)d_in[14];
    const float* b2        = (const float*)d_in[15];
    float* out = (float*)d_out;

    const int* src = edge_idx;
    const int* dst = edge_idx + NE;

    hist_pre_kernel<<<NE / 256 + 1, 256>>>(dst, edge_embs, W_edges, att_edge,
                                           node_emb, Ws, att_src, att_dst);
    scanfill_kernel<<<NBLK, 256>>>(x);
    scatter_kernel<<<(NE + 255) / 256, 256>>>(src, dst, edge_attr);

    agg_kernel<<<(NN * 32 + 127) / 128, 128>>>(0);   // launch #4 -> profiled
    for (int l = 1; l < LL; l++) {
        gemm_kernel<<<(NN + 63) / 64, 256>>>(l, Ws, att_src, att_dst, biases);
        agg_kernel<<<(NN * 32 + 127) / 128, 128>>>(l);
    }

    poolmlp_kernel<<<GG, 256>>>(batch, biases, W1, b1, W2, b2, out);
}

// round 8
// speedup vs baseline: 1.9534x; 1.0125x over previous
#include <cuda_runtime.h>

#define NN 50000
#define NE 800000
#define D 64
#define LL 4
#define GG 128
#define TT 10
#define NEG_SLOPE 0.2f
#define EPSV 1e-16f
#define NBLK ((NN + 255) / 256)   // 196
#define NV 21                     // node vocab size
#define NORMB 12500               // normal agg blocks (warp per node, 4/block)
#define BIGB 8                    // trailing agg blocks for deg>32 nodes
#define MAXBIG 8192

// ---------------- scratch (static __device__, zero-init at load) ----------------
__device__ int   g_deg[NN];        // zeroed by scatter_kernel at end of each run
__device__ int   g_rowptr[NN + 1];
__device__ int   g_cursor[NN];
__device__ unsigned g_epoch;                    // monotonic run counter
__device__ volatile unsigned g_aggflag[NBLK];   // epoch-tagged publish flags
__device__ volatile int      g_aggval[NBLK];
__device__ int   g_bigcnt;
__device__ int   g_biglist[MAXBIG];
__device__ int   g_csr[NE];        // packed (attr<<24) | src
__device__ float g_alpha[NE];      // big-node fallback scratch
__device__ float g_hA[NN * D];
__device__ float g_hB[NN * D];
__device__ float g_gbuf[NN * D];
__device__ float g_asrc[NN];
__device__ float g_adst[NN];
__device__ float g_ewalpha[LL * 4];
__device__ float g_gt[NV * D];     // layer-0 g table
__device__ float g_ast[NV];        // layer-0 asrc table
__device__ float g_adt[NV];        // layer-0 adst table

// ---------------- hist (4 edges/thread) + epoch + ewalpha + layer-0 table ----------------
__global__ void hist_pre_kernel(const int* __restrict__ dst,
                                const float* __restrict__ edge_embs,
                                const float* __restrict__ W_edges,
                                const float* __restrict__ att_edge,
                                const float* __restrict__ node_emb,
                                const float* __restrict__ Ws,
                                const float* __restrict__ att_src,
                                const float* __restrict__ att_dst) {
    int tid = threadIdx.x;
    int t = blockIdx.x * 256 + tid;
    int e = t * 4;
    if (e < NE) {   // NE % 4 == 0, so full int4 is safe
        int4 d = *(const int4*)(dst + e);
        atomicAdd(&g_deg[d.x], 1);
        atomicAdd(&g_deg[d.y], 1);
        atomicAdd(&g_deg[d.z], 1);
        atomicAdd(&g_deg[d.w], 1);
    }
    if (blockIdx.x == 0 && tid == 0) atomicAdd(&g_epoch, 1u);

    if (blockIdx.x == gridDim.x - 1) {
        if (tid == 0) g_bigcnt = 0;
        __shared__ float sv[LL][D];
        __shared__ float sgt[NV][D];
        int l = tid >> 6, j = tid & 63;
        float v = 0.f;
        #pragma unroll
        for (int k = 0; k < D; k++)
            v += att_edge[l * D + k] * W_edges[l * D * D + k * D + j];
        sv[l][j] = v;
        int vg = tid >> 6;
        for (int vv = vg; vv < NV; vv += 4) {
            float acc = 0.f;
            #pragma unroll
            for (int k = 0; k < D; k++)
                acc = fmaf(node_emb[vv * D + k], Ws[j * D + k], acc);
            sgt[vv][j] = acc;
            g_gt[vv * D + j] = acc;
        }
        __syncthreads();
        if (tid < 16) {
            int ll = tid >> 2, a = tid & 3;
            float s = 0.f;
            for (int jj = 0; jj < D; jj++)
                s += edge_embs[ll * 4 * D + a * D + jj] * sv[ll][jj];
            g_ewalpha[ll * 4 + a] = s;
        }
        if (tid < NV) {
            float s = 0.f, dd = 0.f;
            #pragma unroll
            for (int jj = 0; jj < D; jj++) {
                s  += sgt[tid][jj] * att_src[jj];
                dd += sgt[tid][jj] * att_dst[jj];
            }
            g_ast[tid] = s;
            g_adt[tid] = dd;
        }
    }
}

// ---------------- single-kernel scan (publish + spin) + layer-0 fill + big-list ----------------
__global__ void scanfill_kernel(const int* __restrict__ x) {
    __shared__ int wsum[8];
    __shared__ int soffset;
    __shared__ __align__(16) float sgt[NV * D];
    int tid = threadIdx.x, lane = tid & 31, warp = tid >> 5;
    int b = blockIdx.x;
    unsigned epoch = g_epoch;

    int idx = b * 256 + tid;
    int v = (idx < NN) ? g_deg[idx] : 0;
    int xx = v;
    #pragma unroll
    for (int off = 1; off < 32; off <<= 1) {
        int t = __shfl_up_sync(0xFFFFFFFFu, xx, off);
        if (lane >= off) xx += t;
    }
    if (lane == 31) wsum[warp] = xx;
    __syncthreads();
    if (tid < 8) {
        int s = wsum[tid];
        #pragma unroll
        for (int off = 1; off < 8; off <<= 1) {
            int t = __shfl_up_sync(0xFFu, s, off);
            if (tid >= off) s += t;
        }
        wsum[tid] = s;
    }
    __syncthreads();
    int incl = xx + (warp ? wsum[warp - 1] : 0);

    if (tid == 255) {
        g_aggval[b] = incl;
        __threadfence();
        g_aggflag[b] = epoch;
    }
    if (warp == 0) {
        int sum = 0;
        for (int jj = lane; jj < b; jj += 32) {
            while (g_aggflag[jj] < epoch) { }
            sum += g_aggval[jj];
        }
        #pragma unroll
        for (int off = 16; off; off >>= 1)
            sum += __shfl_xor_sync(0xFFFFFFFFu, sum, off);
        if (lane == 0) soffset = sum;
    }
    __syncthreads();
    int r = incl + soffset;
    if (idx < NN) {
        g_rowptr[idx + 1] = r;
        g_cursor[idx] = r - v;
        if (v > 32) {
            int pos = atomicAdd(&g_bigcnt, 1);
            if (pos < MAXBIG) g_biglist[pos] = idx;
        }
    }
    if (b == 0 && tid == 0) g_rowptr[0] = 0;

    // ---- layer-0 fill: gbuf/asrc/adst from tables ----
    for (int i = tid; i < NV * D; i += 256) sgt[i] = g_gt[i];
    __syncthreads();
    if (idx < NN) {
        int xv = x[idx];
        g_asrc[idx] = g_ast[xv];
        g_adst[idx] = g_adt[xv];
    }
    int nb = b * 256;
    for (int i = tid; i < 256 * 16; i += 256) {
        int nl = i >> 4, q = i & 15;
        int node = nb + nl;
        if (node < NN) {
            int xv = __ldg(&x[node]);
            ((float4*)g_gbuf)[node * 16 + q] = ((const float4*)sgt)[xv * 16 + q];
        }
    }
}

// ---------------- scatter: 4 edges/thread (+ zero g_deg) ----------------
__global__ void scatter_kernel(const int* __restrict__ src,
                               const int* __restrict__ dst,
                               const int* __restrict__ attr) {
    int t = blockIdx.x * blockDim.x + threadIdx.x;
    int e = t * 4;
    if (e < NE) {
        int4 s = *(const int4*)(src + e);
        int4 d = *(const int4*)(dst + e);
        int4 a = *(const int4*)(attr + e);
        int p0 = atomicAdd(&g_cursor[d.x], 1);
        int p1 = atomicAdd(&g_cursor[d.y], 1);
        int p2 = atomicAdd(&g_cursor[d.z], 1);
        int p3 = atomicAdd(&g_cursor[d.w], 1);
        g_csr[p0] = (a.x << 24) | s.x;
        g_csr[p1] = (a.y << 24) | s.y;
        g_csr[p2] = (a.z << 24) | s.z;
        g_csr[p3] = (a.w << 24) | s.w;
    }
    if (t < NN) g_deg[t] = 0;
}

// ---------------- per-layer node GEMM (layers 1..3): 4x4 register-tiled ----------------
__global__ void __launch_bounds__(256) gemm_kernel(
        int layer,
        const float* __restrict__ Ws,
        const float* __restrict__ att_src,
        const float* __restrict__ att_dst,
        const float* __restrict__ biases) {
    __shared__ __align__(16) float shT[64][68];
    __shared__ __align__(16) float sWT[64][68];
    __shared__ float sred[2][16][64];

    const float* W = Ws + layer * D * D;
    const float* in_h = (((layer - 1) & 1) == 0) ? g_hA : g_hB;
    const float* bias = biases + (layer - 1) * D;
    const float* a_s = att_src + layer * D;
    const float* a_d = att_dst + layer * D;

    int tid = threadIdx.x;
    int nb = blockIdx.x * 64;

    for (int idx = tid; idx < D * D; idx += 256) {
        sWT[idx & 63][idx >> 6] = W[idx];
    }
    for (int idx = tid; idx < 64 * D; idx += 256) {
        int nl = idx >> 6, k = idx & 63;
        int node = nb + nl;
        float hv = 0.f;
        if (node < NN)
            hv = fmaxf(in_h[node * D + k] + bias[k], 0.f);
        shT[k][nl] = hv;
    }
    __syncthreads();

    int tx = tid & 15;
    int ty = tid >> 4;
    int n0 = tx * 4;
    int j0 = ty * 4;

    float acc[4][4] = {};
    #pragma unroll 8
    for (int k = 0; k < 64; k++) {
        float4 hv = *(const float4*)&shT[k][n0];
        float4 wv = *(const float4*)&sWT[k][j0];
        acc[0][0] = fmaf(hv.x, wv.x, acc[0][0]);
        acc[0][1] = fmaf(hv.x, wv.y, acc[0][1]);
        acc[0][2] = fmaf(hv.x, wv.z, acc[0][2]);
        acc[0][3] = fmaf(hv.x, wv.w, acc[0][3]);
        acc[1][0] = fmaf(hv.y, wv.x, acc[1][0]);
        acc[1][1] = fmaf(hv.y, wv.y, acc[1][1]);
        acc[1][2] = fmaf(hv.y, wv.z, acc[1][2]);
        acc[1][3] = fmaf(hv.y, wv.w, acc[1][3]);
        acc[2][0] = fmaf(hv.z, wv.x, acc[2][0]);
        acc[2][1] = fmaf(hv.z, wv.y, acc[2][1]);
        acc[2][2] = fmaf(hv.z, wv.z, acc[2][2]);
        acc[2][3] = fmaf(hv.z, wv.w, acc[2][3]);
        acc[3][0] = fmaf(hv.w, wv.x, acc[3][0]);
        acc[3][1] = fmaf(hv.w, wv.y, acc[3][1]);
        acc[3][2] = fmaf(hv.w, wv.z, acc[3][2]);
        acc[3][3] = fmaf(hv.w, wv.w, acc[3][3]);
    }

    float as0 = a_s[j0], as1 = a_s[j0 + 1], as2 = a_s[j0 + 2], as3 = a_s[j0 + 3];
    float ad0 = a_d[j0], ad1 = a_d[j0 + 1], ad2 = a_d[j0 + 2], ad3 = a_d[j0 + 3];
    #pragma unroll
    for (int i = 0; i < 4; i++) {
        float sa = acc[i][0] * as0 + acc[i][1] * as1 + acc[i][2] * as2 + acc[i][3] * as3;
        float sd = acc[i][0] * ad0 + acc[i][1] * ad1 + acc[i][2] * ad2 + acc[i][3] * ad3;
        sred[0][ty][n0 + i] = sa;
        sred[1][ty][n0 + i] = sd;
        int node = nb + n0 + i;
        if (node < NN) {
            *(float4*)&g_gbuf[node * D + j0] =
                make_float4(acc[i][0], acc[i][1], acc[i][2], acc[i][3]);
        }
    }
    __syncthreads();
    if (tid < 64) {
        float s = 0.f, dsum = 0.f;
        #pragma unroll
        for (int t = 0; t < 16; t++) {
            s    += sred[0][t][tid];
            dsum += sred[1][t][tid];
        }
        int node = nb + tid;
        if (node < NN) { g_asrc[node] = s; g_adst[node] = dsum; }
    }
}

// ---------------- aggregation ----------------
// blocks [0, NORMB): warp per node, deg<=32 hot path only.
// blocks [NORMB, NORMB+BIGB): drain g_biglist (deg>32) via 3-pass fallback.
__global__ void __launch_bounds__(128) agg_kernel(int layer) {
    const unsigned F = 0xFFFFFFFFu;
    int lane = threadIdx.x & 31;
    const float* ewa = g_ewalpha + layer * 4;
    float* out_h = ((layer & 1) == 0) ? g_hA : g_hB;
    int half  = lane >> 4;
    int qlane = lane & 15;
    const float* gb = g_gbuf + (qlane << 2);
    float4 acc4 = make_float4(0.f, 0.f, 0.f, 0.f);

    if (blockIdx.x >= NORMB) {
        // -------- big-node path --------
        int gw = (blockIdx.x - NORMB) * 4 + (threadIdx.x >> 5);
        int cnt = g_bigcnt;
        if (cnt > MAXBIG) cnt = MAXBIG;
        for (int i = gw; i < cnt; i += BIGB * 4) {
            int n = g_biglist[i];
            int start = g_rowptr[n];
            int end   = g_rowptr[n + 1];
            float adst_n = g_adst[n];
            float m = -1e30f;
            for (int e = start + lane; e < end; e += 32) {
                int p = g_csr[e];
                float a = g_asrc[p & 0x00FFFFFF] + adst_n + ewa[p >> 24];
                a = (a > 0.f) ? a : NEG_SLOPE * a;
                g_alpha[e] = a;
                m = fmaxf(m, a);
            }
            #pragma unroll
            for (int off = 16; off; off >>= 1)
                m = fmaxf(m, __shfl_xor_sync(F, m, off));
            float s = 0.f;
            for (int e = start + lane; e < end; e += 32) {
                float ex = __expf(g_alpha[e] - m);
                g_alpha[e] = ex;
                s += ex;
            }
            #pragma unroll
            for (int off = 16; off; off >>= 1)
                s += __shfl_xor_sync(F, s, off);
            float inv = 1.f / (s + EPSV);

            float4 acc = make_float4(0.f, 0.f, 0.f, 0.f);
            for (int base = start; base < end; base += 32) {
                int c = min(32, end - base);
                float w = 0.f; int boff = 0;
                if (lane < c) {
                    int p = g_csr[base + lane];
                    boff = (p & 0x00FFFFFF) << 8;
                    w = g_alpha[base + lane] * inv;
                }
                for (int t = 0; t < c; t += 2) {
                    int e0 = (t + half) & 31;
                    float w0 = __shfl_sync(F, w, e0);
                    int   b0 = __shfl_sync(F, boff, e0);
                    float4 v0 = *(const float4*)((const char*)gb + b0);
                    acc.x = fmaf(w0, v0.x, acc.x);
                    acc.y = fmaf(w0, v0.y, acc.y);
                    acc.z = fmaf(w0, v0.z, acc.z);
                    acc.w = fmaf(w0, v0.w, acc.w);
                }
            }
            acc.x += __shfl_xor_sync(F, acc.x, 16);
            acc.y += __shfl_xor_sync(F, acc.y, 16);
            acc.z += __shfl_xor_sync(F, acc.z, 16);
            acc.w += __shfl_xor_sync(F, acc.w, 16);
            if (half == 0)
                *(float4*)(out_h + n * D + (qlane << 2)) = acc;
        }
        return;
    }

    // -------- hot path: warp per node, deg <= 32 --------
    int n = blockIdx.x * 4 + (threadIdx.x >> 5);
    if (n >= NN) return;
    int start = g_rowptr[n];
    int deg   = g_rowptr[n + 1] - start;
    if (deg > 32) return;                       // handled by big path
    if (deg == 0) {
        if (half == 0)
            *(float4*)(out_h + n * D + (qlane << 2)) = acc4;
        return;
    }

    float adst_n = g_adst[n];
    int p = 0;
    float a = -1e30f;
    if (lane < deg) {
        p = __ldg(&g_csr[start + lane]);
        a = g_asrc[p & 0x00FFFFFF] + adst_n + ewa[p >> 24];
        a = (a > 0.f) ? a : NEG_SLOPE * a;
    }
    float m = a;
    #pragma unroll
    for (int off = 16; off; off >>= 1)
        m = fmaxf(m, __shfl_xor_sync(F, m, off));
    float ex = __expf(a - m);                   // invalid lanes -> 0
    float s = ex;
    #pragma unroll
    for (int off = 16; off; off >>= 1)
        s += __shfl_xor_sync(F, s, off);
    float w = ex * (1.f / (s + EPSV));          // invalid lanes: 0
    int boff = (p & 0x00FFFFFF) << 8;           // byte offset of row

    // straight-line 8-edge blocks; padded lanes carry w=0 (harmless FMA).
#define EDGE8(T) { \
        int e0 = ((T)     + half) & 31; \
        int e1 = ((T) + 2 + half) & 31; \
        int e2 = ((T) + 4 + half) & 31; \
        int e3 = ((T) + 6 + half) & 31; \
        float w0 = __shfl_sync(F, w, e0);  int b0 = __shfl_sync(F, boff, e0); \
        float w1 = __shfl_sync(F, w, e1);  int b1 = __shfl_sync(F, boff, e1); \
        float w2 = __shfl_sync(F, w, e2);  int b2 = __shfl_sync(F, boff, e2); \
        float w3 = __shfl_sync(F, w, e3);  int b3 = __shfl_sync(F, boff, e3); \
        float4 v0 = *(const float4*)((const char*)gb + b0); \
        float4 v1 = *(const float4*)((const char*)gb + b1); \
        float4 v2 = *(const float4*)((const char*)gb + b2); \
        float4 v3 = *(const float4*)((const char*)gb + b3); \
        acc4.x = fmaf(w0, v0.x, acc4.x); acc4.y = fmaf(w0, v0.y, acc4.y); \
        acc4.z = fmaf(w0, v0.z, acc4.z); acc4.w = fmaf(w0, v0.w, acc4.w); \
        acc4.x = fmaf(w1, v1.x, acc4.x); acc4.y = fmaf(w1, v1.y, acc4.y); \
        acc4.z = fmaf(w1, v1.z, acc4.z); acc4.w = fmaf(w1, v1.w, acc4.w); \
        acc4.x = fmaf(w2, v2.x, acc4.x); acc4.y = fmaf(w2, v2.y, acc4.y); \
        acc4.z = fmaf(w2, v2.z, acc4.z); acc4.w = fmaf(w2, v2.w, acc4.w); \
        acc4.x = fmaf(w3, v3.x, acc4.x); acc4.y = fmaf(w3, v3.y, acc4.y); \
        acc4.z = fmaf(w3, v3.z, acc4.z); acc4.w = fmaf(w3, v3.w, acc4.w); \
    }

    if (deg <= 16) {
        EDGE8(0) EDGE8(8)
    } else if (deg <= 24) {
        EDGE8(0) EDGE8(8) EDGE8(16)
    } else {
        EDGE8(0) EDGE8(8) EDGE8(16) EDGE8(24)
    }
#undef EDGE8

    acc4.x += __shfl_xor_sync(F, acc4.x, 16);
    acc4.y += __shfl_xor_sync(F, acc4.y, 16);
    acc4.z += __shfl_xor_sync(F, acc4.z, 16);
    acc4.w += __shfl_xor_sync(F, acc4.w, 16);
    if (half == 0)
        *(float4*)(out_h + n * D + (qlane << 2)) = acc4;
}

// ---------------- fused pooling + MLP: one block per graph ----------------
__global__ void __launch_bounds__(256) poolmlp_kernel(
        const int* __restrict__ batch,
        const float* __restrict__ biases,
        const float* __restrict__ W1, const float* __restrict__ b1,
        const float* __restrict__ W2, const float* __restrict__ b2,
        float* __restrict__ out) {
    __shared__ float sacc[4][D];
    __shared__ float sp[D];
    __shared__ float shid[2 * D];
    int g = blockIdx.x;
    int tid = threadIdx.x;   // 256

    int lo = 0, hi = NN;
    while (lo < hi) { int mid = (lo + hi) >> 1; if (batch[mid] < g) lo = mid + 1; else hi = mid; }
    int startn = lo;
    hi = NN;
    while (lo < hi) { int mid = (lo + hi) >> 1; if (batch[mid] <= g) lo = mid + 1; else hi = mid; }
    int endn = lo;

    int j = tid & 63, rg = tid >> 6;
    float bj = biases[3 * D + j];
    float acc = 0.f;
    for (int nn = startn + rg; nn < endn; nn += 4)
        acc += fmaxf(g_hB[nn * D + j] + bj, 0.f);
    sacc[rg][j] = acc;
    __syncthreads();
    if (tid < D)
        sp[tid] = sacc[0][tid] + sacc[1][tid] + sacc[2][tid] + sacc[3][tid];
    __syncthreads();
    if (tid < 2 * D) {
        float hsum = b1[tid];
        #pragma unroll
        for (int k = 0; k < D; k++)
            hsum = fmaf(sp[k], W1[tid * D + k], hsum);
        shid[tid] = fmaxf(hsum, 0.f);
    }
    __syncthreads();
    if (tid < TT) {
        float o = b2[tid];
        #pragma unroll
        for (int k = 0; k < 2 * D; k++)
            o = fmaf(shid[k], W2[tid * 2 * D + k], o);
        out[g * TT + tid] = o;
    }
}

// ---------------- launch ----------------
extern "C" void kernel_launch(void* const* d_in, const int* in_sizes, int n_in,
                              void* d_out, int out_size) {
    const int*   x         = (const int*)  d_in[0];
    const int*   edge_idx  = (const int*)  d_in[1];
    const int*   edge_attr = (const int*)  d_in[2];
    const int*   batch     = (const int*)  d_in[3];
    const float* node_emb  = (const float*)d_in[4];
    const float* edge_embs = (const float*)d_in[5];
    const float* Ws        = (const float*)d_in[6];
    const float* W_edges   = (const float*)d_in[7];
    const float* att_src   = (const float*)d_in[8];
    const float* att_dst   = (const float*)d_in[9];
    const float* att_edge  = (const float*)d_in[10];
    const float* biases    = (const float*)d_in[11];
    const float* W1        = (const float*)d_in[12];
    const float* b1        = (const float*)d_in[13];
    const float* W2        = (const float*)d_in[14];
    const float* b2        = (const float*)d_in[15];
    float* out = (float*)d_out;

    const int* src = edge_idx;
    const int* dst = edge_idx + NE;

    int ethreads = NE / 4;                       // 200000
    int eblocks  = (ethreads + 255) / 256;       // 782

    hist_pre_kernel<<<eblocks + 1, 256>>>(dst, edge_embs, W_edges, att_edge,
                                          node_emb, Ws, att_src, att_dst);
    scanfill_kernel<<<NBLK, 256>>>(x);
    scatter_kernel<<<eblocks, 256>>>(src, dst, edge_attr);

    agg_kernel<<<NORMB + BIGB, 128>>>(0);   // launch #4 -> profiled
    for (int l = 1; l < LL; l++) {
        gemm_kernel<<<(NN + 63) / 64, 256>>>(l, Ws, att_src, att_dst, biases);
        agg_kernel<<<NORMB + BIGB, 128>>>(l);
    }

    poolmlp_kernel<<<GG, 256>>>(batch, biases, W1, b1, W2, b2, out);
}

// round 9
// speedup vs baseline: 1.9716x; 1.0093x over previous
#include <cuda_runtime.h>
#include <cuda_fp16.h>

#define NN 50000
#define NE 800000
#define D 64
#define LL 4
#define GG 128
#define TT 10
#define NEG_SLOPE 0.2f
#define EPSV 1e-16f
#define NBLK ((NN + 255) / 256)   // 196
#define NV 21                     // node vocab size
#define NORMB 12500               // normal agg blocks (warp per node, 4/block)
#define BIGB 8                    // trailing agg blocks for deg>32 nodes
#define MAXBIG 8192

// ---------------- scratch (static __device__, zero-init at load) ----------------
__device__ int   g_deg[NN];        // zeroed by scatter_kernel at end of each run
__device__ int   g_rowptr[NN + 1];
__device__ int   g_cursor[NN];
__device__ unsigned g_epoch;                    // monotonic run counter
__device__ volatile unsigned g_aggflag[NBLK];   // epoch-tagged publish flags
__device__ volatile int      g_aggval[NBLK];
__device__ int   g_bigcnt;
__device__ int   g_biglist[MAXBIG];
__device__ int   g_csr[NE];        // packed (attr<<24) | src
__device__ float g_alpha[NE];      // big-node fallback scratch
__device__ float g_hA[NN * D];
__device__ float g_hB[NN * D];
__device__ __align__(16) __half g_gbuf16[NN * D];   // g in fp16 (1 line / row)
__device__ float g_asrc[NN];
__device__ float g_adst[NN];
__device__ float g_ewalpha[LL * 4];
__device__ __align__(16) __half g_gt16[NV * D];     // layer-0 g table (fp16)
__device__ float g_ast[NV];        // layer-0 asrc table
__device__ float g_adt[NV];        // layer-0 adst table

// ---------------- hist (4 edges/thread) + epoch + ewalpha + layer-0 table ----------------
__global__ void hist_pre_kernel(const int* __restrict__ dst,
                                const float* __restrict__ edge_embs,
                                const float* __restrict__ W_edges,
                                const float* __restrict__ att_edge,
                                const float* __restrict__ node_emb,
                                const float* __restrict__ Ws,
                                const float* __restrict__ att_src,
                                const float* __restrict__ att_dst) {
    int tid = threadIdx.x;
    int t = blockIdx.x * 256 + tid;
    int e = t * 4;
    if (e < NE) {   // NE % 4 == 0
        int4 d = *(const int4*)(dst + e);
        atomicAdd(&g_deg[d.x], 1);
        atomicAdd(&g_deg[d.y], 1);
        atomicAdd(&g_deg[d.z], 1);
        atomicAdd(&g_deg[d.w], 1);
    }
    if (blockIdx.x == 0 && tid == 0) atomicAdd(&g_epoch, 1u);

    if (blockIdx.x == gridDim.x - 1) {
        if (tid == 0) g_bigcnt = 0;
        __shared__ float sv[LL][D];
        __shared__ float sgt[NV][D];
        int l = tid >> 6, j = tid & 63;
        float v = 0.f;
        #pragma unroll
        for (int k = 0; k < D; k++)
            v += att_edge[l * D + k] * W_edges[l * D * D + k * D + j];
        sv[l][j] = v;
        int vg = tid >> 6;
        for (int vv = vg; vv < NV; vv += 4) {
            float acc = 0.f;
            #pragma unroll
            for (int k = 0; k < D; k++)
                acc = fmaf(node_emb[vv * D + k], Ws[j * D + k], acc);
            sgt[vv][j] = acc;
            g_gt16[vv * D + j] = __float2half_rn(acc);
        }
        __syncthreads();
        if (tid < 16) {
            int ll = tid >> 2, a = tid & 3;
            float s = 0.f;
            for (int jj = 0; jj < D; jj++)
                s += edge_embs[ll * 4 * D + a * D + jj] * sv[ll][jj];
            g_ewalpha[ll * 4 + a] = s;
        }
        if (tid < NV) {
            float s = 0.f, dd = 0.f;
            #pragma unroll
            for (int jj = 0; jj < D; jj++) {
                s  += sgt[tid][jj] * att_src[jj];
                dd += sgt[tid][jj] * att_dst[jj];
            }
            g_ast[tid] = s;
            g_adt[tid] = dd;
        }
    }
}

// ---------------- single-kernel scan (publish + spin) + layer-0 fill + big-list ----------------
__global__ void scanfill_kernel(const int* __restrict__ x) {
    __shared__ int wsum[8];
    __shared__ int soffset;
    __shared__ __align__(16) __half shalf[NV * D];   // fp16 layer-0 table
    int tid = threadIdx.x, lane = tid & 31, warp = tid >> 5;
    int b = blockIdx.x;
    unsigned epoch = g_epoch;

    int idx = b * 256 + tid;
    int v = (idx < NN) ? g_deg[idx] : 0;
    int xx = v;
    #pragma unroll
    for (int off = 1; off < 32; off <<= 1) {
        int t = __shfl_up_sync(0xFFFFFFFFu, xx, off);
        if (lane >= off) xx += t;
    }
    if (lane == 31) wsum[warp] = xx;
    __syncthreads();
    if (tid < 8) {
        int s = wsum[tid];
        #pragma unroll
        for (int off = 1; off < 8; off <<= 1) {
            int t = __shfl_up_sync(0xFFu, s, off);
            if (tid >= off) s += t;
        }
        wsum[tid] = s;
    }
    __syncthreads();
    int incl = xx + (warp ? wsum[warp - 1] : 0);

    if (tid == 255) {
        g_aggval[b] = incl;
        __threadfence();
        g_aggflag[b] = epoch;
    }
    if (warp == 0) {
        int sum = 0;
        for (int jj = lane; jj < b; jj += 32) {
            while (g_aggflag[jj] < epoch) { }
            sum += g_aggval[jj];
        }
        #pragma unroll
        for (int off = 16; off; off >>= 1)
            sum += __shfl_xor_sync(0xFFFFFFFFu, sum, off);
        if (lane == 0) soffset = sum;
    }
    __syncthreads();
    int r = incl + soffset;
    if (idx < NN) {
        g_rowptr[idx + 1] = r;
        g_cursor[idx] = r - v;
        if (v > 32) {
            int pos = atomicAdd(&g_bigcnt, 1);
            if (pos < MAXBIG) g_biglist[pos] = idx;
        }
    }
    if (b == 0 && tid == 0) g_rowptr[0] = 0;

    // ---- layer-0 fill: gbuf16/asrc/adst from tables ----
    // NV*D halves = 1344 = 168 uint4
    for (int i = tid; i < (NV * D) / 8; i += 256)
        ((uint4*)shalf)[i] = ((const uint4*)g_gt16)[i];
    __syncthreads();
    if (idx < NN) {
        int xv = x[idx];
        g_asrc[idx] = g_ast[xv];
        g_adst[idx] = g_adt[xv];
    }
    int nb = b * 256;
    // each node row = 128B = 8 uint4
    for (int i = tid; i < 256 * 8; i += 256) {
        int nl = i >> 3, q = i & 7;
        int node = nb + nl;
        if (node < NN) {
            int xv = __ldg(&x[node]);
            ((uint4*)g_gbuf16)[node * 8 + q] = ((const uint4*)shalf)[xv * 8 + q];
        }
    }
}

// ---------------- scatter: 4 edges/thread (+ zero g_deg) ----------------
__global__ void scatter_kernel(const int* __restrict__ src,
                               const int* __restrict__ dst,
                               const int* __restrict__ attr) {
    int t = blockIdx.x * blockDim.x + threadIdx.x;
    int e = t * 4;
    if (e < NE) {
        int4 s = *(const int4*)(src + e);
        int4 d = *(const int4*)(dst + e);
        int4 a = *(const int4*)(attr + e);
        int p0 = atomicAdd(&g_cursor[d.x], 1);
        int p1 = atomicAdd(&g_cursor[d.y], 1);
        int p2 = atomicAdd(&g_cursor[d.z], 1);
        int p3 = atomicAdd(&g_cursor[d.w], 1);
        g_csr[p0] = (a.x << 24) | s.x;
        g_csr[p1] = (a.y << 24) | s.y;
        g_csr[p2] = (a.z << 24) | s.z;
        g_csr[p3] = (a.w << 24) | s.w;
    }
    if (t < NN) g_deg[t] = 0;
}

// ---------------- per-layer node GEMM (layers 1..3): 4x4 register-tiled ----------------
__global__ void __launch_bounds__(256) gemm_kernel(
        int layer,
        const float* __restrict__ Ws,
        const float* __restrict__ att_src,
        const float* __restrict__ att_dst,
        const float* __restrict__ biases) {
    __shared__ __align__(16) float shT[64][68];
    __shared__ __align__(16) float sWT[64][68];
    __shared__ float sred[2][16][64];

    const float* W = Ws + layer * D * D;
    const float* in_h = (((layer - 1) & 1) == 0) ? g_hA : g_hB;
    const float* bias = biases + (layer - 1) * D;
    const float* a_s = att_src + layer * D;
    const float* a_d = att_dst + layer * D;

    int tid = threadIdx.x;
    int nb = blockIdx.x * 64;

    for (int idx = tid; idx < D * D; idx += 256) {
        sWT[idx & 63][idx >> 6] = W[idx];
    }
    for (int idx = tid; idx < 64 * D; idx += 256) {
        int nl = idx >> 6, k = idx & 63;
        int node = nb + nl;
        float hv = 0.f;
        if (node < NN)
            hv = fmaxf(in_h[node * D + k] + bias[k], 0.f);
        shT[k][nl] = hv;
    }
    __syncthreads();

    int tx = tid & 15;
    int ty = tid >> 4;
    int n0 = tx * 4;
    int j0 = ty * 4;

    float acc[4][4] = {};
    #pragma unroll 8
    for (int k = 0; k < 64; k++) {
        float4 hv = *(const float4*)&shT[k][n0];
        float4 wv = *(const float4*)&sWT[k][j0];
        acc[0][0] = fmaf(hv.x, wv.x, acc[0][0]);
        acc[0][1] = fmaf(hv.x, wv.y, acc[0][1]);
        acc[0][2] = fmaf(hv.x, wv.z, acc[0][2]);
        acc[0][3] = fmaf(hv.x, wv.w, acc[0][3]);
        acc[1][0] = fmaf(hv.y, wv.x, acc[1][0]);
        acc[1][1] = fmaf(hv.y, wv.y, acc[1][1]);
        acc[1][2] = fmaf(hv.y, wv.z, acc[1][2]);
        acc[1][3] = fmaf(hv.y, wv.w, acc[1][3]);
        acc[2][0] = fmaf(hv.z, wv.x, acc[2][0]);
        acc[2][1] = fmaf(hv.z, wv.y, acc[2][1]);
        acc[2][2] = fmaf(hv.z, wv.z, acc[2][2]);
        acc[2][3] = fmaf(hv.z, wv.w, acc[2][3]);
        acc[3][0] = fmaf(hv.w, wv.x, acc[3][0]);
        acc[3][1] = fmaf(hv.w, wv.y, acc[3][1]);
        acc[3][2] = fmaf(hv.w, wv.z, acc[3][2]);
        acc[3][3] = fmaf(hv.w, wv.w, acc[3][3]);
    }

    float as0 = a_s[j0], as1 = a_s[j0 + 1], as2 = a_s[j0 + 2], as3 = a_s[j0 + 3];
    float ad0 = a_d[j0], ad1 = a_d[j0 + 1], ad2 = a_d[j0 + 2], ad3 = a_d[j0 + 3];
    #pragma unroll
    for (int i = 0; i < 4; i++) {
        float sa = acc[i][0] * as0 + acc[i][1] * as1 + acc[i][2] * as2 + acc[i][3] * as3;
        float sd = acc[i][0] * ad0 + acc[i][1] * ad1 + acc[i][2] * ad2 + acc[i][3] * ad3;
        sred[0][ty][n0 + i] = sa;
        sred[1][ty][n0 + i] = sd;
        int node = nb + n0 + i;
        if (node < NN) {
            __half2 h01 = __floats2half2_rn(acc[i][0], acc[i][1]);
            __half2 h23 = __floats2half2_rn(acc[i][2], acc[i][3]);
            uint2 u;
            u.x = *(unsigned*)&h01;
            u.y = *(unsigned*)&h23;
            *(uint2*)&g_gbuf16[node * D + j0] = u;   // 8B aligned (j0 % 4 == 0)
        }
    }
    __syncthreads();
    if (tid < 64) {
        float s = 0.f, dsum = 0.f;
        #pragma unroll
        for (int t = 0; t < 16; t++) {
            s    += sred[0][t][tid];
            dsum += sred[1][t][tid];
        }
        int node = nb + tid;
        if (node < NN) { g_asrc[node] = s; g_adst[node] = dsum; }
    }
}

// ---------------- aggregation ----------------
// blocks [0, NORMB): warp per node, deg<=32 hot path only.
// blocks [NORMB, NORMB+BIGB): drain g_biglist (deg>32) via 3-pass fallback.
__global__ void __launch_bounds__(128) agg_kernel(int layer) {
    const unsigned F = 0xFFFFFFFFu;
    int lane = threadIdx.x & 31;
    const float* ewa = g_ewalpha + layer * 4;
    float* out_h = ((layer & 1) == 0) ? g_hA : g_hB;
    int half  = lane >> 4;
    int qlane = lane & 15;
    const char* gb16 = (const char*)g_gbuf16 + (qlane << 3);  // 8B per lane
    float4 acc4 = make_float4(0.f, 0.f, 0.f, 0.f);

    if (blockIdx.x >= NORMB) {
        // -------- big-node path --------
        int gw = (blockIdx.x - NORMB) * 4 + (threadIdx.x >> 5);
        int cnt = g_bigcnt;
        if (cnt > MAXBIG) cnt = MAXBIG;
        for (int i = gw; i < cnt; i += BIGB * 4) {
            int n = g_biglist[i];
            int start = g_rowptr[n];
            int end   = g_rowptr[n + 1];
            float adst_n = g_adst[n];
            float m = -1e30f;
            for (int e = start + lane; e < end; e += 32) {
                int p = g_csr[e];
                float a = g_asrc[p & 0x00FFFFFF] + adst_n + ewa[p >> 24];
                a = (a > 0.f) ? a : NEG_SLOPE * a;
                g_alpha[e] = a;
                m = fmaxf(m, a);
            }
            #pragma unroll
            for (int off = 16; off; off >>= 1)
                m = fmaxf(m, __shfl_xor_sync(F, m, off));
            float s = 0.f;
            for (int e = start + lane; e < end; e += 32) {
                float ex = __expf(g_alpha[e] - m);
                g_alpha[e] = ex;
                s += ex;
            }
            #pragma unroll
            for (int off = 16; off; off >>= 1)
                s += __shfl_xor_sync(F, s, off);
            float inv = 1.f / (s + EPSV);

            float4 acc = make_float4(0.f, 0.f, 0.f, 0.f);
            for (int base = start; base < end; base += 32) {
                int c = min(32, end - base);
                float w = 0.f; int boff = 0;
                if (lane < c) {
                    int p = g_csr[base + lane];
                    boff = (p & 0x00FFFFFF) << 7;   // 128B rows
                    w = g_alpha[base + lane] * inv;
                }
                for (int t = 0; t < c; t += 2) {
                    int e0 = (t + half) & 31;
                    float w0 = __shfl_sync(F, w, e0);
                    int   b0 = __shfl_sync(F, boff, e0);
                    uint2 u = *(const uint2*)(gb16 + b0);
                    float2 f0 = __half22float2(*(__half2*)&u.x);
                    float2 f1 = __half22float2(*(__half2*)&u.y);
                    acc.x = fmaf(w0, f0.x, acc.x);
                    acc.y = fmaf(w0, f0.y, acc.y);
                    acc.z = fmaf(w0, f1.x, acc.z);
                    acc.w = fmaf(w0, f1.y, acc.w);
                }
            }
            acc.x += __shfl_xor_sync(F, acc.x, 16);
            acc.y += __shfl_xor_sync(F, acc.y, 16);
            acc.z += __shfl_xor_sync(F, acc.z, 16);
            acc.w += __shfl_xor_sync(F, acc.w, 16);
            if (half == 0)
                *(float4*)(out_h + n * D + (qlane << 2)) = acc;
        }
        return;
    }

    // -------- hot path: warp per node, deg <= 32 --------
    int n = blockIdx.x * 4 + (threadIdx.x >> 5);
    if (n >= NN) return;
    int start = g_rowptr[n];
    int deg   = g_rowptr[n + 1] - start;
    if (deg > 32) return;                       // handled by big path
    if (deg == 0) {
        if (half == 0)
            *(float4*)(out_h + n * D + (qlane << 2)) = acc4;
        return;
    }

    float adst_n = g_adst[n];
    int p = 0;
    float a = -1e30f;
    if (lane < deg) {
        p = __ldg(&g_csr[start + lane]);
        a = g_asrc[p & 0x00FFFFFF] + adst_n + ewa[p >> 24];
        a = (a > 0.f) ? a : NEG_SLOPE * a;
    }
    float m = a;
    #pragma unroll
    for (int off = 16; off; off >>= 1)
        m = fmaxf(m, __shfl_xor_sync(F, m, off));
    float ex = __expf(a - m);                   // invalid lanes -> 0
    float s = ex;
    #pragma unroll
    for (int off = 16; off; off >>= 1)
        s += __shfl_xor_sync(F, s, off);
    float w = ex * (1.f / (s + EPSV));          // invalid lanes: 0
    int boff = (p & 0x00FFFFFF) << 7;           // byte offset of fp16 row

    // straight-line 8-edge blocks; padded lanes carry w=0 (harmless FMA).
#define EDGE8(T) { \
        int e0 = ((T)     + half) & 31; \
        int e1 = ((T) + 2 + half) & 31; \
        int e2 = ((T) + 4 + half) & 31; \
        int e3 = ((T) + 6 + half) & 31; \
        float w0 = __shfl_sync(F, w, e0);  int b0 = __shfl_sync(F, boff, e0); \
        float w1 = __shfl_sync(F, w, e1);  int b1 = __shfl_sync(F, boff, e1); \
        float w2 = __shfl_sync(F, w, e2);  int b2 = __shfl_sync(F, boff, e2); \
        float w3 = __shfl_sync(F, w, e3);  int b3 = __shfl_sync(F, boff, e3); \
        uint2 u0 = *(const uint2*)(gb16 + b0); \
        uint2 u1 = *(const uint2*)(gb16 + b1); \
        uint2 u2 = *(const uint2*)(gb16 + b2); \
        uint2 u3 = *(const uint2*)(gb16 + b3); \
        float2 f0a = __half22float2(*(__half2*)&u0.x); \
        float2 f0b = __half22float2(*(__half2*)&u0.y); \
        float2 f1a = __half22float2(*(__half2*)&u1.x); \
        float2 f1b = __half22float2(*(__half2*)&u1.y); \
        float2 f2a = __half22float2(*(__half2*)&u2.x); \
        float2 f2b = __half22float2(*(__half2*)&u2.y); \
        float2 f3a = __half22float2(*(__half2*)&u3.x); \
        float2 f3b = __half22float2(*(__half2*)&u3.y); \
        acc4.x = fmaf(w0, f0a.x, acc4.x); acc4.y = fmaf(w0, f0a.y, acc4.y); \
        acc4.z = fmaf(w0, f0b.x, acc4.z); acc4.w = fmaf(w0, f0b.y, acc4.w); \
        acc4.x = fmaf(w1, f1a.x, acc4.x); acc4.y = fmaf(w1, f1a.y, acc4.y); \
        acc4.z = fmaf(w1, f1b.x, acc4.z); acc4.w = fmaf(w1, f1b.y, acc4.w); \
        acc4.x = fmaf(w2, f2a.x, acc4.x); acc4.y = fmaf(w2, f2a.y, acc4.y); \
        acc4.z = fmaf(w2, f2b.x, acc4.z); acc4.w = fmaf(w2, f2b.y, acc4.w); \
        acc4.x = fmaf(w3, f3a.x, acc4.x); acc4.y = fmaf(w3, f3a.y, acc4.y); \
        acc4.z = fmaf(w3, f3b.x, acc4.z); acc4.w = fmaf(w3, f3b.y, acc4.w); \
    }

    if (deg <= 16) {
        EDGE8(0) EDGE8(8)
    } else if (deg <= 24) {
        EDGE8(0) EDGE8(8) EDGE8(16)
    } else {
        EDGE8(0) EDGE8(8) EDGE8(16) EDGE8(24)
    }
#undef EDGE8

    acc4.x += __shfl_xor_sync(F, acc4.x, 16);
    acc4.y += __shfl_xor_sync(F, acc4.y, 16);
    acc4.z += __shfl_xor_sync(F, acc4.z, 16);
    acc4.w += __shfl_xor_sync(F, acc4.w, 16);
    if (half == 0)
        *(float4*)(out_h + n * D + (qlane << 2)) = acc4;
}

// ---------------- fused pooling + MLP: one block per graph ----------------
__global__ void __launch_bounds__(256) poolmlp_kernel(
        const int* __restrict__ batch,
        const float* __restrict__ biases,
        const float* __restrict__ W1, const float* __restrict__ b1,
        const float* __restrict__ W2, const float* __restrict__ b2,
        float* __restrict__ out) {
    __shared__ float sacc[4][D];
    __shared__ float sp[D];
    __shared__ float shid[2 * D];
    int g = blockIdx.x;
    int tid = threadIdx.x;   // 256

    int lo = 0, hi = NN;
    while (lo < hi) { int mid = (lo + hi) >> 1; if (batch[mid] < g) lo = mid + 1; else hi = mid; }
    int startn = lo;
    hi = NN;
    while (lo < hi) { int mid = (lo + hi) >> 1; if (batch[mid] <= g) lo = mid + 1; else hi = mid; }
    int endn = lo;

    int j = tid & 63, rg = tid >> 6;
    float bj = biases[3 * D + j];
    float acc = 0.f;
    for (int nn = startn + rg; nn < endn; nn += 4)
        acc += fmaxf(g_hB[nn * D + j] + bj, 0.f);
    sacc[rg][j] = acc;
    __syncthreads();
    if (tid < D)
        sp[tid] = sacc[0][tid] + sacc[1][tid] + sacc[2][tid] + sacc[3][tid];
    __syncthreads();
    if (tid < 2 * D) {
        float hsum = b1[tid];
        #pragma unroll
        for (int k = 0; k < D; k++)
            hsum = fmaf(sp[k], W1[tid * D + k], hsum);
        shid[tid] = fmaxf(hsum, 0.f);
    }
    __syncthreads();
    if (tid < TT) {
        float o = b2[tid];
        #pragma unroll
        for (int k = 0; k < 2 * D; k++)
            o = fmaf(shid[k], W2[tid * 2 * D + k], o);
        out[g * TT + tid] = o;
    }
}

// ---------------- launch ----------------
extern "C" void kernel_launch(void* const* d_in, const int* in_sizes, int n_in,
                              void* d_out, int out_size) {
    const int*   x         = (const int*)  d_in[0];
    const int*   edge_idx  = (const int*)  d_in[1];
    const int*   edge_attr = (const int*)  d_in[2];
    const int*   batch     = (const int*)  d_in[3];
    const float* node_emb  = (const float*)d_in[4];
    const float* edge_embs = (const float*)d_in[5];
    const float* Ws        = (const float*)d_in[6];
    const float* W_edges   = (const float*)d_in[7];
    const float* att_src   = (const float*)d_in[8];
    const float* att_dst   = (const float*)d_in[9];
    const float* att_edge  = (const float*)d_in[10];
    const float* biases    = (const float*)d_in[11];
    const float* W1        = (const float*)d_in[12];
    const float* b1        = (const float*)d_in[13];
    const float* W2        = (const float*)d_in[14];
    const float* b2        = (const float*)d_in[15];
    float* out = (float*)d_out;

    const int* src = edge_idx;
    const int* dst = edge_idx + NE;

    int ethreads = NE / 4;                       // 200000
    int eblocks  = (ethreads + 255) / 256;       // 782

    hist_pre_kernel<<<eblocks + 1, 256>>>(dst, edge_embs, W_edges, att_edge,
                                          node_emb, Ws, att_src, att_dst);
    scanfill_kernel<<<NBLK, 256>>>(x);
    scatter_kernel<<<eblocks, 256>>>(src, dst, edge_attr);

    agg_kernel<<<NORMB + BIGB, 128>>>(0);   // launch #4 -> profiled
    for (int l = 1; l < LL; l++) {
        gemm_kernel<<<(NN + 63) / 64, 256>>>(l, Ws, att_src, att_dst, biases);
        agg_kernel<<<NORMB + BIGB, 128>>>(l);
    }

    poolmlp_kernel<<<GG, 256>>>(batch, biases, W1, b1, W2, b2, out);
}